// round 2
// baseline (speedup 1.0000x reference)
#include <cuda_runtime.h>
#include <math_constants.h>

#define BB 8
#define NN 1024
#define KK 20

// ---------------- scratch (device globals: no allocation allowed) ----------------
__device__ float d_f0[BB * 3 * NN];            // layer-0 features (B,3,N)
__device__ float d_x1[BB * 21 * 3 * NN];
__device__ float d_x2[BB * 21 * 3 * NN];
__device__ float d_x3[BB * 42 * 3 * NN];
__device__ float d_x4[BB * 85 * 3 * NN];
__device__ int   d_knnIdx[BB * NN * KK];
__device__ float d_h5[BB * 1023 * NN];
__device__ float d_g [BB * 2046];
__device__ float d_g1[BB * 512];
__device__ float d_g2[BB * 256];

// ---------------- transpose x (B,N,3) -> f0 (B,3,N) ----------------
__global__ void transpose_kernel(const float* __restrict__ x) {
    int i = blockIdx.x * blockDim.x + threadIdx.x;
    if (i >= BB * NN * 3) return;
    int b = i / (NN * 3);
    int r = i - b * (NN * 3);
    int n = r / 3;
    int j = r - n * 3;
    d_f0[((size_t)b * 3 + j) * NN + n] = x[i];
}

// ---------------- KNN: one block (256 thr) per (b,n). D = flat channel count ----------------
// dist kept in registers (4 per thread). 20 argmax passes, 2 syncs each.
template <int D>
__global__ void knn_kernel(const float* __restrict__ feat) {
    int b = blockIdx.x >> 10;
    int n = blockIdx.x & (NN - 1);
    const float* f = feat + (size_t)b * D * NN;

    __shared__ float ctr[D];
    __shared__ float warpv[8];
    __shared__ int   warpi[8];
    __shared__ int   s_win;

    int t = threadIdx.x;
    int lane = t & 31, wid = t >> 5;

    for (int d = t; d < D; d += 256) ctr[d] = f[(size_t)d * NN + n];
    __syncthreads();

    float sqn = 0.f;
#pragma unroll 4
    for (int d = 0; d < D; d++) sqn += ctr[d] * ctr[d];

    float dist[4];
#pragma unroll
    for (int j = 0; j < 4; j++) {
        int m = t + 256 * j;
        float inner = 0.f, sqm = 0.f;
#pragma unroll 4
        for (int d = 0; d < D; d++) {
            float v = f[(size_t)d * NN + m];
            inner += ctr[d] * v;
            sqm   += v * v;
        }
        dist[j] = 2.f * inner - sqn - sqm;   // neg squared distance
    }

    for (int k = 0; k < KK; k++) {
        float v = dist[0]; int bi = t;
#pragma unroll
        for (int j = 1; j < 4; j++) {
            if (dist[j] > v) { v = dist[j]; bi = t + 256 * j; }  // strict >: smallest m wins
        }
#pragma unroll
        for (int off = 16; off; off >>= 1) {
            float ov = __shfl_down_sync(0xffffffffu, v, off);
            int   oi = __shfl_down_sync(0xffffffffu, bi, off);
            if (ov > v || (ov == v && oi < bi)) { v = ov; bi = oi; }
        }
        if (lane == 0) { warpv[wid] = v; warpi[wid] = bi; }
        __syncthreads();
        if (t < 8) {
            v = warpv[t]; bi = warpi[t];
#pragma unroll
            for (int off = 4; off; off >>= 1) {
                float ov = __shfl_down_sync(0xffu, v, off);
                int   oi = __shfl_down_sync(0xffu, bi, off);
                if (ov > v || (ov == v && oi < bi)) { v = ov; bi = oi; }
            }
            if (t == 0) {
                d_knnIdx[((size_t)b * NN + n) * KK + k] = bi;
                s_win = bi;
            }
        }
        __syncthreads();
        int w = s_win;
        if ((w & 255) == t) dist[w >> 8] = -CUDART_INF_F;
    }
}

// ---------------- EdgeConv: graph feature + vn_leaky + vn_max_pool fused ----------------
// Input feat (B,C,3,N); output (B,O,3,N). One block per (b,n); thread t owns channel o=t.
template <int C, int O, int T>
__global__ void edge_kernel(const float* __restrict__ feat,
                            const float* __restrict__ Wp, const float* __restrict__ Wd,
                            const float* __restrict__ Wm, float* __restrict__ out) {
    constexpr int C2 = 2 * C;
    int b = blockIdx.x >> 10;
    int n = blockIdx.x & (NN - 1);
    int t = threadIdx.x;
    const float* f = feat + (size_t)b * C * 3 * NN;

    __shared__ float ctr[C * 3];
    __shared__ float e[C2 * 3];
    __shared__ float h[O * 3];
    __shared__ int   kidx[KK];

    for (int i = t; i < C * 3; i += T) ctr[i] = f[(size_t)i * NN + n];
    if (t < KK) kidx[t] = d_knnIdx[((size_t)b * NN + n) * KK + t];
    __syncthreads();

    int o = t;
    float bestdot = -CUDART_INF_F;
    float bh0 = 0.f, bh1 = 0.f, bh2 = 0.f;

    for (int k = 0; k < KK; k++) {
        int m = kidx[k];
        for (int i = t; i < C * 3; i += T) {
            float nb = f[(size_t)i * NN + m];
            float c0 = ctr[i];
            e[i] = nb - c0;         // channels [0,C): nbr - ctr
            e[C * 3 + i] = c0;      // channels [C,2C): ctr
        }
        __syncthreads();

        if (o < O) {
            float p0 = 0.f, p1 = 0.f, p2 = 0.f, q0 = 0.f, q1 = 0.f, q2 = 0.f;
#pragma unroll 4
            for (int c = 0; c < C2; c++) {
                float wp = Wp[o * C2 + c];
                float wd = Wd[o * C2 + c];
                float e0 = e[c * 3], e1 = e[c * 3 + 1], e2 = e[c * 3 + 2];
                p0 += wp * e0; p1 += wp * e1; p2 += wp * e2;
                q0 += wd * e0; q1 += wd * e1; q2 += wd * e2;
            }
            float dot = p0 * q0 + p1 * q1 + p2 * q2;
            float h0, h1, h2;
            if (dot >= 0.f) {
                h0 = p0; h1 = p1; h2 = p2;
            } else {
                float dsq = q0 * q0 + q1 * q1 + q2 * q2;
                float cth = 0.8f * dot / (dsq + 1e-6f);
                h0 = p0 - cth * q0; h1 = p1 - cth * q1; h2 = p2 - cth * q2;
            }
            h[o * 3] = h0; h[o * 3 + 1] = h1; h[o * 3 + 2] = h2;
        }
        __syncthreads();

        if (o < O) {
            float m0 = 0.f, m1 = 0.f, m2 = 0.f;
#pragma unroll 4
            for (int c = 0; c < O; c++) {
                float w = Wm[o * O + c];
                m0 += w * h[c * 3]; m1 += w * h[c * 3 + 1]; m2 += w * h[c * 3 + 2];
            }
            float h0 = h[o * 3], h1 = h[o * 3 + 1], h2 = h[o * 3 + 2];
            float pd = h0 * m0 + h1 * m1 + h2 * m2;
            if (pd > bestdot) { bestdot = pd; bh0 = h0; bh1 = h1; bh2 = h2; }  // first max wins
        }
        __syncthreads();
    }

    if (o < O) {
        float* op = out + (((size_t)b * O + o) * 3) * NN + n;
        op[0]      = bh0;
        op[NN]     = bh1;
        op[2 * NN] = bh2;
    }
}

// ---------------- layer 5: vn_leaky on concat(x1..x4), write (B,1023,N) ----------------
__global__ void layer5_kernel(const float* __restrict__ Wp5, const float* __restrict__ Wd5) {
    int b = blockIdx.x >> 10;
    int n = blockIdx.x & (NN - 1);
    int t = threadIdx.x;

    __shared__ float e[169 * 3];

    // gather concat channels: x1[0,21) x2[21,42) x3[42,84) x4[84,169)
    for (int i = t; i < 21 * 3; i += 128) e[i]          = d_x1[((size_t)b * 21 * 3 + i) * NN + n];
    for (int i = t; i < 21 * 3; i += 128) e[21 * 3 + i] = d_x2[((size_t)b * 21 * 3 + i) * NN + n];
    for (int i = t; i < 42 * 3; i += 128) e[42 * 3 + i] = d_x3[((size_t)b * 42 * 3 + i) * NN + n];
    for (int i = t; i < 85 * 3; i += 128) e[84 * 3 + i] = d_x4[((size_t)b * 85 * 3 + i) * NN + n];
    __syncthreads();

    float d0 = 0.f, d1 = 0.f, d2 = 0.f;
#pragma unroll 4
    for (int c = 0; c < 169; c++) {
        float w = Wd5[c];
        d0 += w * e[c * 3]; d1 += w * e[c * 3 + 1]; d2 += w * e[c * 3 + 2];
    }
    float dsq = d0 * d0 + d1 * d1 + d2 * d2;
    float inv = 0.8f / (dsq + 1e-6f);

    for (int o = t; o < 341; o += 128) {
        float p0 = 0.f, p1 = 0.f, p2 = 0.f;
#pragma unroll 4
        for (int c = 0; c < 169; c++) {
            float w = Wp5[o * 169 + c];
            p0 += w * e[c * 3]; p1 += w * e[c * 3 + 1]; p2 += w * e[c * 3 + 2];
        }
        float dot = p0 * d0 + p1 * d1 + p2 * d2;
        float h0, h1, h2;
        if (dot >= 0.f) { h0 = p0; h1 = p1; h2 = p2; }
        else { float cth = dot * inv; h0 = p0 - cth * d0; h1 = p1 - cth * d1; h2 = p2 - cth * d2; }
        size_t base = (size_t)b * 1023 * NN + (size_t)(o * 3) * NN + n;
        d_h5[base]          = h0;
        d_h5[base + NN]     = h1;
        d_h5[base + 2 * NN] = h2;
    }
}

// ---------------- global max + mean over N ----------------
__global__ void reduce_kernel() {
    int b = blockIdx.x / 1023;
    int ch = blockIdx.x - b * 1023;
    const float* row = d_h5 + (size_t)b * 1023 * NN + (size_t)ch * NN;
    int t = threadIdx.x;
    float mx = -CUDART_INF_F, sm = 0.f;
    for (int m = t; m < NN; m += 128) {
        float v = row[m];
        mx = fmaxf(mx, v);
        sm += v;
    }
    __shared__ float smx[128], ssm[128];
    smx[t] = mx; ssm[t] = sm;
    __syncthreads();
    for (int s = 64; s > 0; s >>= 1) {
        if (t < s) { smx[t] = fmaxf(smx[t], smx[t + s]); ssm[t] += ssm[t + s]; }
        __syncthreads();
    }
    if (t == 0) {
        d_g[b * 2046 + ch]        = smx[0];
        d_g[b * 2046 + 1023 + ch] = ssm[0] * (1.f / NN);
    }
}

// ---------------- FC: one warp per output element ----------------
__global__ void fc_kernel(const float* __restrict__ in, const float* __restrict__ W,
                          const float* __restrict__ bias, float* __restrict__ out,
                          int rows, int icols, int ocols, float slope) {
    int gw = (blockIdx.x * blockDim.x + threadIdx.x) >> 5;
    int lane = threadIdx.x & 31;
    if (gw >= rows * ocols) return;
    int r = gw / ocols;
    int o = gw - r * ocols;
    const float* ir = in + (size_t)r * icols;
    const float* wr = W + (size_t)o * icols;
    float s = 0.f;
    for (int c = lane; c < icols; c += 32) s += ir[c] * wr[c];
#pragma unroll
    for (int off = 16; off; off >>= 1) s += __shfl_down_sync(0xffffffffu, s, off);
    if (lane == 0) {
        s += bias[o];
        if (slope != 1.0f) s = (s >= 0.f) ? s : slope * s;
        out[(size_t)r * ocols + o] = s;
    }
}

// ---------------- launch ----------------
extern "C" void kernel_launch(void* const* d_in, const int* in_sizes, int n_in,
                              void* d_out, int out_size) {
    const float* x   = (const float*)d_in[0];
    const float* Wp1 = (const float*)d_in[1];
    const float* Wd1 = (const float*)d_in[2];
    const float* Wm1 = (const float*)d_in[3];
    const float* Wp2 = (const float*)d_in[4];
    const float* Wd2 = (const float*)d_in[5];
    const float* Wm2 = (const float*)d_in[6];
    const float* Wp3 = (const float*)d_in[7];
    const float* Wd3 = (const float*)d_in[8];
    const float* Wm3 = (const float*)d_in[9];
    const float* Wp4 = (const float*)d_in[10];
    const float* Wd4 = (const float*)d_in[11];
    const float* Wm4 = (const float*)d_in[12];
    const float* Wp5 = (const float*)d_in[13];
    const float* Wd5 = (const float*)d_in[14];
    const float* W1  = (const float*)d_in[15];
    const float* b1  = (const float*)d_in[16];
    const float* W2  = (const float*)d_in[17];
    const float* b2  = (const float*)d_in[18];
    const float* W3  = (const float*)d_in[19];
    const float* b3  = (const float*)d_in[20];

    // device-symbol addresses are linked statically into the kernels; the only
    // pointers passed are harness inputs/outputs.
    float* f0; float* x1; float* x2; float* x3; float* x4;
    float* g; float* g1; float* g2;
    cudaGetSymbolAddress((void**)&f0, d_f0);
    cudaGetSymbolAddress((void**)&x1, d_x1);
    cudaGetSymbolAddress((void**)&x2, d_x2);
    cudaGetSymbolAddress((void**)&x3, d_x3);
    cudaGetSymbolAddress((void**)&x4, d_x4);
    cudaGetSymbolAddress((void**)&g,  d_g);
    cudaGetSymbolAddress((void**)&g1, d_g1);
    cudaGetSymbolAddress((void**)&g2, d_g2);

    transpose_kernel<<<(BB * NN * 3 + 255) / 256, 256>>>(x);

    knn_kernel<3><<<BB * NN, 256>>>(f0);
    edge_kernel<1, 21, 32><<<BB * NN, 32>>>(f0, Wp1, Wd1, Wm1, x1);

    knn_kernel<63><<<BB * NN, 256>>>(x1);
    edge_kernel<21, 21, 32><<<BB * NN, 32>>>(x1, Wp2, Wd2, Wm2, x2);

    knn_kernel<63><<<BB * NN, 256>>>(x2);
    edge_kernel<21, 42, 64><<<BB * NN, 64>>>(x2, Wp3, Wd3, Wm3, x3);

    knn_kernel<126><<<BB * NN, 256>>>(x3);
    edge_kernel<42, 85, 96><<<BB * NN, 96>>>(x3, Wp4, Wd4, Wm4, x4);

    layer5_kernel<<<BB * NN, 128>>>(Wp5, Wd5);
    reduce_kernel<<<BB * 1023, 128>>>();

    fc_kernel<<<(8 * 512 * 32 + 255) / 256, 256>>>(g,  W1, b1, g1, 8, 2046, 512, 0.01f);
    fc_kernel<<<(8 * 256 * 32 + 255) / 256, 256>>>(g1, W2, b2, g2, 8, 512,  256, 0.01f);
    fc_kernel<<<(8 * 128 * 32 + 255) / 256, 256>>>(g2, W3, b3, (float*)d_out, 8, 256, 128, 1.0f);
}

// round 6
// speedup vs baseline: 4.1784x; 4.1784x over previous
#include <cuda_runtime.h>
#include <math_constants.h>

#define BB 8
#define NN 1024
#define KK 20

// ---------------- scratch (device globals: no allocation allowed) ----------------
__device__ float d_f0[BB * 3 * NN];            // (B,3,N)
__device__ float d_x1[BB * 21 * 3 * NN];
__device__ float d_x2[BB * 21 * 3 * NN];
__device__ float d_x3[BB * 42 * 3 * NN];
__device__ float d_x4[BB * 85 * 3 * NN];
__device__ int   d_knnIdx[BB * NN * KK];
__device__ float d_pad[BB * NN * 3 * 85 * 2 + 16];  // per-point (pa,da), layout (B,N,3,O,2)
__device__ float d_ctr[BB * NN * 3 * 85 * 2 + 16];  // per-point (pb,db)
__device__ float d_wp5t[169 * 341];
__device__ float d_h5[BB * 1023 * NN];
__device__ float d_g [BB * 2046];
__device__ float d_g1[BB * 512];
__device__ float d_g2[BB * 256];

// ---------------- transpose x (B,N,3) -> f0 (B,3,N) ----------------
__global__ void transpose_kernel(const float* __restrict__ x) {
    int i = blockIdx.x * blockDim.x + threadIdx.x;
    if (i >= BB * NN * 3) return;
    int b = i / (NN * 3);
    int r = i - b * (NN * 3);
    int n = r / 3;
    int j = r - n * 3;
    d_f0[((size_t)b * 3 + j) * NN + n] = x[i];
}

// ---------------- transpose Wp5 (341,169) -> (169,341) ----------------
__global__ void transpose_w5(const float* __restrict__ Wp5) {
    int i = blockIdx.x * blockDim.x + threadIdx.x;
    if (i >= 341 * 169) return;
    int o = i / 169, c = i - o * 169;
    d_wp5t[c * 341 + o] = Wp5[i];
}

// ---------------- KNN: one block (256 thr) per (b,n); float4 over m ----------------
template <int D>
__global__ void __launch_bounds__(256) knn_kernel(const float* __restrict__ feat) {
    int b = blockIdx.x >> 10;
    int n = blockIdx.x & (NN - 1);
    const float* f = feat + (size_t)b * D * NN;

    __shared__ float ctr[D];
    __shared__ float warpv[8];
    __shared__ int   warpi[8];
    __shared__ int   s_win;

    int t = threadIdx.x;
    int lane = t & 31, wid = t >> 5;

    for (int d = t; d < D; d += 256) ctr[d] = f[(size_t)d * NN + n];
    __syncthreads();

    float sqn = 0.f;
#pragma unroll 4
    for (int d = 0; d < D; d++) sqn += ctr[d] * ctr[d];

    float in0 = 0.f, in1 = 0.f, in2 = 0.f, in3 = 0.f;
    float sq0 = 0.f, sq1 = 0.f, sq2 = 0.f, sq3 = 0.f;
    const float4* fp = (const float4*)(f) + t;     // element 4t of row 0
#pragma unroll 2
    for (int d = 0; d < D; d++) {
        float c = ctr[d];
        float4 v = fp[(size_t)d * (NN / 4)];
        in0 += c * v.x; sq0 += v.x * v.x;
        in1 += c * v.y; sq1 += v.y * v.y;
        in2 += c * v.z; sq2 += v.z * v.z;
        in3 += c * v.w; sq3 += v.w * v.w;
    }
    float dist[4];
    dist[0] = 2.f * in0 - sqn - sq0;
    dist[1] = 2.f * in1 - sqn - sq1;
    dist[2] = 2.f * in2 - sqn - sq2;
    dist[3] = 2.f * in3 - sqn - sq3;

    for (int k = 0; k < KK; k++) {
        float v = dist[0]; int bi = 4 * t;
#pragma unroll
        for (int j = 1; j < 4; j++) {
            if (dist[j] > v) { v = dist[j]; bi = 4 * t + j; }  // strict >: smallest m wins
        }
#pragma unroll
        for (int off = 16; off; off >>= 1) {
            float ov = __shfl_down_sync(0xffffffffu, v, off);
            int   oi = __shfl_down_sync(0xffffffffu, bi, off);
            if (ov > v || (ov == v && oi < bi)) { v = ov; bi = oi; }
        }
        if (lane == 0) { warpv[wid] = v; warpi[wid] = bi; }
        __syncthreads();
        if (t < 8) {
            v = warpv[t]; bi = warpi[t];
#pragma unroll
            for (int off = 4; off; off >>= 1) {
                float ov = __shfl_down_sync(0xffu, v, off);
                int   oi = __shfl_down_sync(0xffu, bi, off);
                if (ov > v || (ov == v && oi < bi)) { v = ov; bi = oi; }
            }
            if (t == 0) {
                d_knnIdx[((size_t)b * NN + n) * KK + k] = bi;
                s_win = bi;
            }
        }
        __syncthreads();
        int w = s_win;
        if ((w >> 2) == t) dist[w & 3] = -CUDART_INF_F;
    }
}

// ---------------- per-point GEMM: pa = Wl x, pb = (Wr-Wl) x (same for d) ----------------
// x: (B,C,3,N). Output pad/ctr layout: (B,N,3,O,2) with (p.,d.) interleaved.
// Two passes (p then d) reusing one shared weight pair to stay under 48KB smem.
template <int C, int O>
__global__ void __launch_bounds__(96) gemm_pd(const float* __restrict__ x,
                                              const float* __restrict__ Wp,
                                              const float* __restrict__ Wd,
                                              float* __restrict__ pad,
                                              float* __restrict__ ctrb) {
    constexpr int C2 = 2 * C;
    constexpr int Cp = (C + 1) & ~1;
    __shared__ float A[O * Cp], Bw[O * Cp];

    int b = blockIdx.x / (NN / 32);
    int tile = blockIdx.x % (NN / 32);
    int t = threadIdx.x;

    int n = tile * 32 + (t & 31);
    int ax = t >> 5;
    float xr[Cp];
#pragma unroll
    for (int c = 0; c < C; c++)
        xr[c] = x[(((size_t)b * C + c) * 3 + ax) * NN + n];
    if (Cp > C) xr[Cp - 1] = 0.f;

    size_t obase = (((size_t)(b * NN + n) * 3 + ax) * O) * 2;

#pragma unroll
    for (int pass = 0; pass < 2; pass++) {
        const float* W = pass ? Wd : Wp;
        __syncthreads();      // protect prior-pass reads of A/Bw
        for (int i = t; i < O * Cp; i += 96) {
            int o = i / Cp, c = i - o * Cp;
            float av = 0.f, bv = 0.f;
            if (c < C) {
                float wl = W[o * C2 + c], wr = W[o * C2 + C + c];
                av = wl; bv = wr - wl;
            }
            A[i] = av; Bw[i] = bv;
        }
        __syncthreads();

        for (int o = 0; o < O; o++) {
            float pa = 0.f, pb = 0.f;
#pragma unroll
            for (int c = 0; c < Cp; c += 2) {
                float2 a  = *(const float2*)&A[o * Cp + c];
                float2 bq = *(const float2*)&Bw[o * Cp + c];
                float x0 = xr[c], x1 = xr[c + 1];
                pa += a.x * x0 + a.y * x1;
                pb += bq.x * x0 + bq.y * x1;
            }
            pad[obase + o * 2 + pass]  = pa;
            ctrb[obase + o * 2 + pass] = pb;
        }
    }
}

// ---------------- edge combine + leaky + learned max-pool ----------------
// One warp per point, NP=4 points per block. OPT outputs per lane.
template <int O, int OPT>
__global__ void __launch_bounds__(128) edge_combine(const float* __restrict__ pad,
                                                    const float* __restrict__ ctrb,
                                                    const float* __restrict__ Wm,
                                                    float* __restrict__ out) {
    constexpr int NP = 4;
    constexpr int AT = (O + OPT - 1) / OPT;   // active lanes
    constexpr int Opad = AT * OPT;

    __shared__ float  WmT[O * Opad];
    __shared__ float4 h4s[NP][Opad];
    __shared__ int    kk[NP][KK];

    int b = blockIdx.x / (NN / NP);
    int ptile = blockIdx.x % (NN / NP);
    int t = threadIdx.x;
    int w = t >> 5, lane = t & 31;

    for (int i = t; i < O * O; i += 32 * NP) {
        int o = i / O, c = i - o * O;
        WmT[c * Opad + o] = Wm[i];
    }
    if constexpr (Opad > O) {
        for (int i = t; i < O * (Opad - O); i += 32 * NP) {
            int c = i / (Opad - O), j = i - c * (Opad - O);
            WmT[c * Opad + O + j] = 0.f;
        }
    }
    int n = ptile * NP + w;
    if (lane < KK) kk[w][lane] = d_knnIdx[((size_t)b * NN + n) * KK + lane];
    __syncthreads();

    bool act = lane < AT;
    float pb[OPT][3], db[OPT][3];
    size_t cbase = ((size_t)(b * NN + n) * 3) * (O * 2);
    if (act) {
#pragma unroll
        for (int j = 0; j < OPT; j++) {
            int o = lane * OPT + j;
#pragma unroll
            for (int ax = 0; ax < 3; ax++) {
                float2 v = *(const float2*)&ctrb[cbase + (size_t)ax * (O * 2) + o * 2];
                pb[j][ax] = v.x; db[j][ax] = v.y;
            }
        }
    }

    float best[OPT];
    float bh[OPT][3];
#pragma unroll
    for (int j = 0; j < OPT; j++) { best[j] = -CUDART_INF_F; bh[j][0] = bh[j][1] = bh[j][2] = 0.f; }

    for (int k = 0; k < KK; k++) {
        int m = kk[w][k];
        float h[OPT][3];
        if (act) {
            size_t gbase = ((size_t)(b * NN + m) * 3) * (O * 2);
#pragma unroll
            for (int j = 0; j < OPT; j++) {
                int o = lane * OPT + j;
                float2 v0 = *(const float2*)&pad[gbase + 0 * (O * 2) + o * 2];
                float2 v1 = *(const float2*)&pad[gbase + 1 * (O * 2) + o * 2];
                float2 v2 = *(const float2*)&pad[gbase + 2 * (O * 2) + o * 2];
                float p0 = v0.x + pb[j][0], q0 = v0.y + db[j][0];
                float p1 = v1.x + pb[j][1], q1 = v1.y + db[j][1];
                float p2 = v2.x + pb[j][2], q2 = v2.y + db[j][2];
                float dot = p0 * q0 + p1 * q1 + p2 * q2;
                float h0, h1, h2;
                if (dot >= 0.f) {
                    h0 = p0; h1 = p1; h2 = p2;
                } else {
                    float dsq = q0 * q0 + q1 * q1 + q2 * q2;
                    float cth = 0.8f * dot / (dsq + 1e-6f);
                    h0 = p0 - cth * q0; h1 = p1 - cth * q1; h2 = p2 - cth * q2;
                }
                h[j][0] = h0; h[j][1] = h1; h[j][2] = h2;
                h4s[w][lane * OPT + j] = make_float4(h0, h1, h2, 0.f);
            }
        }
        __syncwarp();
        if (act) {
            float mv[OPT][3];
#pragma unroll
            for (int j = 0; j < OPT; j++) mv[j][0] = mv[j][1] = mv[j][2] = 0.f;
#pragma unroll 4
            for (int c = 0; c < O; c++) {
                float4 hc = h4s[w][c];
#pragma unroll
                for (int j = 0; j < OPT; j++) {
                    float wv = WmT[c * Opad + lane * OPT + j];
                    mv[j][0] += wv * hc.x;
                    mv[j][1] += wv * hc.y;
                    mv[j][2] += wv * hc.z;
                }
            }
#pragma unroll
            for (int j = 0; j < OPT; j++) {
                float pd = h[j][0] * mv[j][0] + h[j][1] * mv[j][1] + h[j][2] * mv[j][2];
                if (pd > best[j]) {
                    best[j] = pd;
                    bh[j][0] = h[j][0]; bh[j][1] = h[j][1]; bh[j][2] = h[j][2];
                }
            }
        }
        __syncwarp();
    }

    if (act) {
#pragma unroll
        for (int j = 0; j < OPT; j++) {
            int o = lane * OPT + j;
            if (o < O) {
                float* op = out + (((size_t)b * O + o) * 3) * NN + n;
                op[0]      = bh[j][0];
                op[NN]     = bh[j][1];
                op[2 * NN] = bh[j][2];
            }
        }
    }
}

// ---------------- layer 5: vn_leaky on concat(x1..x4) -> (B,1023,N) ----------------
__global__ void __launch_bounds__(352) layer5_kernel(const float* __restrict__ Wd5) {
    constexpr int NP = 4;
    __shared__ float4 es[NP][169];
    __shared__ float dvs[NP][4];

    int b = blockIdx.x / (NN / NP);
    int tile = blockIdx.x % (NN / NP);
    int t = threadIdx.x;

    for (int idx = t; idx < NP * 169; idx += 352) {
        int p = idx / 169, c = idx - p * 169;
        int n = tile * NP + p;
        const float* src; int cc, CL;
        if (c < 21)      { src = d_x1; cc = c;      CL = 21; }
        else if (c < 42) { src = d_x2; cc = c - 21; CL = 21; }
        else if (c < 84) { src = d_x3; cc = c - 42; CL = 42; }
        else             { src = d_x4; cc = c - 84; CL = 85; }
        size_t base = (((size_t)b * CL + cc) * 3) * NN + n;
        es[p][c] = make_float4(src[base], src[base + NN], src[base + 2 * NN], 0.f);
    }
    __syncthreads();

    if (t < NP) {
        int p = t;
        float s0 = 0.f, s1 = 0.f, s2 = 0.f;
        for (int c = 0; c < 169; c++) {
            float wv = Wd5[c];
            float4 e = es[p][c];
            s0 += wv * e.x; s1 += wv * e.y; s2 += wv * e.z;
        }
        dvs[p][0] = s0; dvs[p][1] = s1; dvs[p][2] = s2;
        dvs[p][3] = 0.8f / (s0 * s0 + s1 * s1 + s2 * s2 + 1e-6f);
    }
    __syncthreads();

    int o = t;
    if (o < 341) {
        float a[NP][3];
#pragma unroll
        for (int p = 0; p < NP; p++) a[p][0] = a[p][1] = a[p][2] = 0.f;
        const float* wc = d_wp5t + o;
#pragma unroll 2
        for (int c = 0; c < 169; c++) {
            float wv = wc[(size_t)c * 341];
#pragma unroll
            for (int p = 0; p < NP; p++) {
                float4 e = es[p][c];
                a[p][0] += wv * e.x; a[p][1] += wv * e.y; a[p][2] += wv * e.z;
            }
        }
#pragma unroll
        for (int p = 0; p < NP; p++) {
            int n = tile * NP + p;
            float dot = a[p][0] * dvs[p][0] + a[p][1] * dvs[p][1] + a[p][2] * dvs[p][2];
            float h0, h1, h2;
            if (dot >= 0.f) { h0 = a[p][0]; h1 = a[p][1]; h2 = a[p][2]; }
            else {
                float cth = dot * dvs[p][3];
                h0 = a[p][0] - cth * dvs[p][0];
                h1 = a[p][1] - cth * dvs[p][1];
                h2 = a[p][2] - cth * dvs[p][2];
            }
            size_t base = ((size_t)b * 1023 + o * 3) * NN + n;
            d_h5[base]          = h0;
            d_h5[base + NN]     = h1;
            d_h5[base + 2 * NN] = h2;
        }
    }
}

// ---------------- global max + mean over N ----------------
__global__ void reduce_kernel() {
    int b = blockIdx.x / 1023;
    int ch = blockIdx.x - b * 1023;
    const float* row = d_h5 + (size_t)b * 1023 * NN + (size_t)ch * NN;
    int t = threadIdx.x;
    float mx = -CUDART_INF_F, sm = 0.f;
    for (int m = t; m < NN; m += 128) {
        float v = row[m];
        mx = fmaxf(mx, v);
        sm += v;
    }
    __shared__ float smx[128], ssm[128];
    smx[t] = mx; ssm[t] = sm;
    __syncthreads();
    for (int s = 64; s > 0; s >>= 1) {
        if (t < s) { smx[t] = fmaxf(smx[t], smx[t + s]); ssm[t] += ssm[t + s]; }
        __syncthreads();
    }
    if (t == 0) {
        d_g[b * 2046 + ch]        = smx[0];
        d_g[b * 2046 + 1023 + ch] = ssm[0] * (1.f / NN);
    }
}

// ---------------- FC: one warp per output element ----------------
__global__ void fc_kernel(const float* __restrict__ in, const float* __restrict__ W,
                          const float* __restrict__ bias, float* __restrict__ out,
                          int rows, int icols, int ocols, float slope) {
    int gw = (blockIdx.x * blockDim.x + threadIdx.x) >> 5;
    int lane = threadIdx.x & 31;
    if (gw >= rows * ocols) return;
    int r = gw / ocols;
    int o = gw - r * ocols;
    const float* ir = in + (size_t)r * icols;
    const float* wr = W + (size_t)o * icols;
    float s = 0.f;
    for (int c = lane; c < icols; c += 32) s += ir[c] * wr[c];
#pragma unroll
    for (int off = 16; off; off >>= 1) s += __shfl_down_sync(0xffffffffu, s, off);
    if (lane == 0) {
        s += bias[o];
        if (slope != 1.0f) s = (s >= 0.f) ? s : slope * s;
        out[(size_t)r * ocols + o] = s;
    }
}

// ---------------- launch ----------------
extern "C" void kernel_launch(void* const* d_in, const int* in_sizes, int n_in,
                              void* d_out, int out_size) {
    const float* x   = (const float*)d_in[0];
    const float* Wp1 = (const float*)d_in[1];
    const float* Wd1 = (const float*)d_in[2];
    const float* Wm1 = (const float*)d_in[3];
    const float* Wp2 = (const float*)d_in[4];
    const float* Wd2 = (const float*)d_in[5];
    const float* Wm2 = (const float*)d_in[6];
    const float* Wp3 = (const float*)d_in[7];
    const float* Wd3 = (const float*)d_in[8];
    const float* Wm3 = (const float*)d_in[9];
    const float* Wp4 = (const float*)d_in[10];
    const float* Wd4 = (const float*)d_in[11];
    const float* Wm4 = (const float*)d_in[12];
    const float* Wp5 = (const float*)d_in[13];
    const float* Wd5 = (const float*)d_in[14];
    const float* W1  = (const float*)d_in[15];
    const float* b1  = (const float*)d_in[16];
    const float* W2  = (const float*)d_in[17];
    const float* b2  = (const float*)d_in[18];
    const float* W3  = (const float*)d_in[19];
    const float* b3  = (const float*)d_in[20];

    float *f0, *x1, *x2, *x3, *x4, *pad, *ctrb, *g, *g1, *g2;
    cudaGetSymbolAddress((void**)&f0,   d_f0);
    cudaGetSymbolAddress((void**)&x1,   d_x1);
    cudaGetSymbolAddress((void**)&x2,   d_x2);
    cudaGetSymbolAddress((void**)&x3,   d_x3);
    cudaGetSymbolAddress((void**)&x4,   d_x4);
    cudaGetSymbolAddress((void**)&pad,  d_pad);
    cudaGetSymbolAddress((void**)&ctrb, d_ctr);
    cudaGetSymbolAddress((void**)&g,    d_g);
    cudaGetSymbolAddress((void**)&g1,   d_g1);
    cudaGetSymbolAddress((void**)&g2,   d_g2);

    transpose_kernel<<<(BB * NN * 3 + 255) / 256, 256>>>(x);
    transpose_w5<<<(341 * 169 + 255) / 256, 256>>>(Wp5);

    knn_kernel<3><<<BB * NN, 256>>>(f0);
    gemm_pd<1, 21><<<BB * (NN / 32), 96>>>(f0, Wp1, Wd1, pad, ctrb);
    edge_combine<21, 1><<<BB * NN / 4, 128>>>(pad, ctrb, Wm1, x1);

    knn_kernel<63><<<BB * NN, 256>>>(x1);
    gemm_pd<21, 21><<<BB * (NN / 32), 96>>>(x1, Wp2, Wd2, pad, ctrb);
    edge_combine<21, 1><<<BB * NN / 4, 128>>>(pad, ctrb, Wm2, x2);

    knn_kernel<63><<<BB * NN, 256>>>(x2);
    gemm_pd<21, 42><<<BB * (NN / 32), 96>>>(x2, Wp3, Wd3, pad, ctrb);
    edge_combine<42, 2><<<BB * NN / 4, 128>>>(pad, ctrb, Wm3, x3);

    knn_kernel<126><<<BB * NN, 256>>>(x3);
    gemm_pd<42, 85><<<BB * (NN / 32), 96>>>(x3, Wp4, Wd4, pad, ctrb);
    edge_combine<85, 3><<<BB * NN / 4, 128>>>(pad, ctrb, Wm4, x4);

    layer5_kernel<<<BB * NN / 4, 352>>>(Wd5);
    reduce_kernel<<<BB * 1023, 128>>>();

    fc_kernel<<<(8 * 512 * 32 + 255) / 256, 256>>>(g,  W1, b1, g1, 8, 2046, 512, 0.01f);
    fc_kernel<<<(8 * 256 * 32 + 255) / 256, 256>>>(g1, W2, b2, g2, 8, 512,  256, 0.01f);
    fc_kernel<<<(8 * 128 * 32 + 255) / 256, 256>>>(g2, W3, b3, (float*)d_out, 8, 256, 128, 1.0f);
}

// round 7
// speedup vs baseline: 4.8692x; 1.1653x over previous
#include <cuda_runtime.h>
#include <math_constants.h>

#define BB 8
#define NN 1024
#define KK 20

// ---------------- scratch (device globals: no allocation allowed) ----------------
__device__ float d_f0[BB * 3 * NN];            // (B,3,N)
__device__ float d_x1[BB * 21 * 3 * NN];
__device__ float d_x2[BB * 21 * 3 * NN];
__device__ float d_x3[BB * 42 * 3 * NN];
__device__ float d_x4[BB * 85 * 3 * NN];
__device__ int   d_knnIdx[BB * NN * KK];
__device__ float d_sqm[BB * NN];
__device__ float d_pad[BB * NN * 85 * 8 + 16];  // per-point, layout (B,N,O,8): [pa0,da0,pa1,da1,pa2,da2,-,-]
__device__ float d_ctr[BB * NN * 85 * 8 + 16];  // per-point (pb,db) same layout
__device__ float d_wp5t[169 * 341];
__device__ float d_h5[BB * 1023 * NN];
__device__ float d_g [BB * 2046];
__device__ float d_g1[BB * 512];
__device__ float d_g2[BB * 256];

// ---------------- transpose x (B,N,3) -> f0 (B,3,N) ----------------
__global__ void transpose_kernel(const float* __restrict__ x) {
    int i = blockIdx.x * blockDim.x + threadIdx.x;
    if (i >= BB * NN * 3) return;
    int b = i / (NN * 3);
    int r = i - b * (NN * 3);
    int n = r / 3;
    int j = r - n * 3;
    d_f0[((size_t)b * 3 + j) * NN + n] = x[i];
}

// ---------------- transpose Wp5 (341,169) -> (169,341) ----------------
__global__ void transpose_w5(const float* __restrict__ Wp5) {
    int i = blockIdx.x * blockDim.x + threadIdx.x;
    if (i >= 341 * 169) return;
    int o = i / 169, c = i - o * 169;
    d_wp5t[c * 341 + o] = Wp5[i];
}

// ---------------- per-point squared norms (same d-ascending FFMA chain as before) ----------------
template <int D>
__global__ void __launch_bounds__(256) sq_kernel(const float* __restrict__ feat) {
    int i = blockIdx.x * 256 + threadIdx.x;
    int b = i >> 10, m = i & (NN - 1);
    const float* f = feat + (size_t)b * D * NN + m;
    float s = 0.f;
#pragma unroll 4
    for (int d = 0; d < D; d++) { float v = f[(size_t)d * NN]; s += v * v; }
    d_sqm[i] = s;
}

// ---------------- KNN: one block (256 thr) per 4 rows; float4 over m ----------------
template <int D>
__global__ void __launch_bounds__(256) knn_kernel(const float* __restrict__ feat) {
    constexpr int NB = 4;
    int b = blockIdx.x / (NN / NB);
    int tile = blockIdx.x % (NN / NB);
    const float* f = feat + (size_t)b * D * NN;

    __shared__ float ctr[NB][D];
    __shared__ float warpv[NB * 8];
    __shared__ int   warpi[NB * 8];
    __shared__ int   s_win[NB];

    int t = threadIdx.x;
    int lane = t & 31, wid = t >> 5;

    for (int i = t; i < NB * D; i += 256) {
        int r = i / D, d = i - r * D;
        ctr[r][d] = f[(size_t)d * NN + tile * NB + r];
    }
    __syncthreads();

    float sqn[NB];
#pragma unroll
    for (int r = 0; r < NB; r++) sqn[r] = d_sqm[b * NN + tile * NB + r];
    float4 sq4 = *(const float4*)&d_sqm[b * NN + 4 * t];

    float acc[NB][4];
#pragma unroll
    for (int r = 0; r < NB; r++)
#pragma unroll
        for (int j = 0; j < 4; j++) acc[r][j] = 0.f;

    const float4* fp = (const float4*)(f) + t;   // element 4t of row 0
    for (int d = 0; d < D; d++) {
        float4 v = fp[(size_t)d * (NN / 4)];
#pragma unroll
        for (int r = 0; r < NB; r++) {
            float c = ctr[r][d];
            acc[r][0] += c * v.x;
            acc[r][1] += c * v.y;
            acc[r][2] += c * v.z;
            acc[r][3] += c * v.w;
        }
    }

    float dist[NB][4];
#pragma unroll
    for (int r = 0; r < NB; r++) {
        dist[r][0] = 2.f * acc[r][0] - sqn[r] - sq4.x;
        dist[r][1] = 2.f * acc[r][1] - sqn[r] - sq4.y;
        dist[r][2] = 2.f * acc[r][2] - sqn[r] - sq4.z;
        dist[r][3] = 2.f * acc[r][3] - sqn[r] - sq4.w;
    }

    for (int k = 0; k < KK; k++) {
        float v[NB]; int bi[NB];
#pragma unroll
        for (int r = 0; r < NB; r++) {
            v[r] = dist[r][0]; bi[r] = 4 * t;
#pragma unroll
            for (int j = 1; j < 4; j++)
                if (dist[r][j] > v[r]) { v[r] = dist[r][j]; bi[r] = 4 * t + j; }  // strict >: smallest m wins
#pragma unroll
            for (int off = 16; off; off >>= 1) {
                float ov = __shfl_down_sync(0xffffffffu, v[r], off);
                int   oi = __shfl_down_sync(0xffffffffu, bi[r], off);
                if (ov > v[r] || (ov == v[r] && oi < bi[r])) { v[r] = ov; bi[r] = oi; }
            }
        }
        if (lane == 0) {
#pragma unroll
            for (int r = 0; r < NB; r++) { warpv[r * 8 + wid] = v[r]; warpi[r * 8 + wid] = bi[r]; }
        }
        __syncthreads();
        if (t < 32) {   // warp 0: 4 aligned 8-lane segments, one per row
            float vv = warpv[t]; int ii = warpi[t];
#pragma unroll
            for (int off = 4; off; off >>= 1) {
                float ov = __shfl_down_sync(0xffffffffu, vv, off);
                int   oi = __shfl_down_sync(0xffffffffu, ii, off);
                if (ov > vv || (ov == vv && oi < ii)) { vv = ov; ii = oi; }
            }
            if ((t & 7) == 0) {
                int r = t >> 3;
                d_knnIdx[((size_t)b * NN + tile * NB + r) * KK + k] = ii;
                s_win[r] = ii;
            }
        }
        __syncthreads();
#pragma unroll
        for (int r = 0; r < NB; r++) {
            int w = s_win[r];
            if ((w >> 2) == t) dist[r][w & 3] = -CUDART_INF_F;
        }
    }
}

// ---------------- per-point GEMM: pa = Wl x, pb = (Wr-Wl) x (same for d); single pass ----------------
// x: (B,C,3,N). Output pad/ctr layout: (B,N,O,8): per o: [p0,d0,p1,d1,p2,d2,-,-].
template <int C, int O>
__global__ void __launch_bounds__(96) gemm_pd(const float* __restrict__ x,
                                              const float* __restrict__ Wp,
                                              const float* __restrict__ Wd,
                                              float* __restrict__ pad,
                                              float* __restrict__ ctrb) {
    constexpr int C2 = 2 * C;
    constexpr int Cp = (C + 1) & ~1;
    extern __shared__ float sw[];
    float* Ap = sw;
    float* Bp = sw + O * Cp;
    float* Ad = sw + 2 * O * Cp;
    float* Bd = sw + 3 * O * Cp;

    int b = blockIdx.x / (NN / 32);
    int tile = blockIdx.x % (NN / 32);
    int t = threadIdx.x;

    for (int i = t; i < O * Cp; i += 96) {
        int o = i / Cp, c = i - o * Cp;
        float apv = 0.f, bpv = 0.f, adv = 0.f, bdv = 0.f;
        if (c < C) {
            float wl = Wp[o * C2 + c], wr = Wp[o * C2 + C + c];
            apv = wl; bpv = wr - wl;
            wl = Wd[o * C2 + c]; wr = Wd[o * C2 + C + c];
            adv = wl; bdv = wr - wl;
        }
        Ap[i] = apv; Bp[i] = bpv; Ad[i] = adv; Bd[i] = bdv;
    }

    int n = tile * 32 + (t & 31);
    int ax = t >> 5;
    float xr[Cp];
#pragma unroll
    for (int c = 0; c < C; c++)
        xr[c] = x[(((size_t)b * C + c) * 3 + ax) * NN + n];
    if (Cp > C) xr[Cp - 1] = 0.f;
    __syncthreads();

    size_t obase = (size_t)(b * NN + n) * (O * 8) + ax * 2;
    for (int o = 0; o < O; o++) {
        float pa = 0.f, pb = 0.f, da = 0.f, db = 0.f;
#pragma unroll
        for (int c = 0; c < Cp; c += 2) {
            float2 a  = *(const float2*)&Ap[o * Cp + c];
            float2 bq = *(const float2*)&Bp[o * Cp + c];
            float2 ad = *(const float2*)&Ad[o * Cp + c];
            float2 bd = *(const float2*)&Bd[o * Cp + c];
            float x0 = xr[c], x1 = xr[c + 1];
            pa += a.x * x0 + a.y * x1;
            pb += bq.x * x0 + bq.y * x1;
            da += ad.x * x0 + ad.y * x1;
            db += bd.x * x0 + bd.y * x1;
        }
        *(float2*)&pad[obase + o * 8]  = make_float2(pa, da);
        *(float2*)&ctrb[obase + o * 8] = make_float2(pb, db);
    }
}

// ---------------- edge combine + leaky + learned max-pool (KC=4 neighbor chunking) ----------------
template <int O, int OPT, int NP>
__global__ void __launch_bounds__(32 * NP) edge_combine(const float* __restrict__ pad,
                                                        const float* __restrict__ ctrb,
                                                        const float* __restrict__ Wm,
                                                        float* __restrict__ out) {
    constexpr int AT = (O + OPT - 1) / OPT;   // active lanes
    constexpr int Opad = AT * OPT;
    constexpr int KC = 4;
    constexpr int T = 32 * NP;

    __shared__ float  WmT[O * Opad];
    __shared__ float4 h4s[NP][KC][Opad];
    __shared__ int    kk[NP][KK];

    int b = blockIdx.x / (NN / NP);
    int ptile = blockIdx.x % (NN / NP);
    int t = threadIdx.x;
    int w = t >> 5, lane = t & 31;

    for (int i = t; i < O * O; i += T) {
        int o = i / O, c = i - o * O;
        WmT[c * Opad + o] = Wm[i];
    }
    if constexpr (Opad > O) {
        for (int i = t; i < O * (Opad - O); i += T) {
            int c = i / (Opad - O), j = i - c * (Opad - O);
            WmT[c * Opad + O + j] = 0.f;
        }
    }
    int n = ptile * NP + w;
    if (lane < KK) kk[w][lane] = d_knnIdx[((size_t)b * NN + n) * KK + lane];
    __syncthreads();

    bool act = lane < AT;
    float pb[OPT][3], db[OPT][3];
    size_t cbase = (size_t)(b * NN + n) * (O * 8);
    if (act) {
#pragma unroll
        for (int j = 0; j < OPT; j++) {
            int o = lane * OPT + j;
            float4 u  = *(const float4*)&ctrb[cbase + o * 8];
            float2 u2 = *(const float2*)&ctrb[cbase + o * 8 + 4];
            pb[j][0] = u.x;  db[j][0] = u.y;
            pb[j][1] = u.z;  db[j][1] = u.w;
            pb[j][2] = u2.x; db[j][2] = u2.y;
        }
    }

    float best[OPT];
    float bh[OPT][3];
#pragma unroll
    for (int j = 0; j < OPT; j++) { best[j] = -CUDART_INF_F; bh[j][0] = bh[j][1] = bh[j][2] = 0.f; }

    for (int chunk = 0; chunk < KK / KC; chunk++) {
#pragma unroll
        for (int kc = 0; kc < KC; kc++) {
            int m = kk[w][chunk * KC + kc];
            if (act) {
                size_t gbase = (size_t)(b * NN + m) * (O * 8);
#pragma unroll
                for (int j = 0; j < OPT; j++) {
                    int o = lane * OPT + j;
                    float4 u  = *(const float4*)&pad[gbase + o * 8];
                    float2 u2 = *(const float2*)&pad[gbase + o * 8 + 4];
                    float p0 = u.x  + pb[j][0], q0 = u.y  + db[j][0];
                    float p1 = u.z  + pb[j][1], q1 = u.w  + db[j][1];
                    float p2 = u2.x + pb[j][2], q2 = u2.y + db[j][2];
                    float dot = p0 * q0 + p1 * q1 + p2 * q2;
                    float h0, h1, h2;
                    if (dot >= 0.f) {
                        h0 = p0; h1 = p1; h2 = p2;
                    } else {
                        float dsq = q0 * q0 + q1 * q1 + q2 * q2;
                        float cth = 0.8f * dot / (dsq + 1e-6f);
                        h0 = p0 - cth * q0; h1 = p1 - cth * q1; h2 = p2 - cth * q2;
                    }
                    h4s[w][kc][lane * OPT + j] = make_float4(h0, h1, h2, 0.f);
                }
            }
        }
        __syncwarp();
        if (act) {
            float mv[OPT][KC][3];
#pragma unroll
            for (int j = 0; j < OPT; j++)
#pragma unroll
                for (int kc = 0; kc < KC; kc++) mv[j][kc][0] = mv[j][kc][1] = mv[j][kc][2] = 0.f;
#pragma unroll 2
            for (int c = 0; c < O; c++) {
                float wv[OPT];
#pragma unroll
                for (int j = 0; j < OPT; j++) wv[j] = WmT[c * Opad + lane * OPT + j];
#pragma unroll
                for (int kc = 0; kc < KC; kc++) {
                    float4 hc = h4s[w][kc][c];
#pragma unroll
                    for (int j = 0; j < OPT; j++) {
                        mv[j][kc][0] += wv[j] * hc.x;
                        mv[j][kc][1] += wv[j] * hc.y;
                        mv[j][kc][2] += wv[j] * hc.z;
                    }
                }
            }
#pragma unroll
            for (int kc = 0; kc < KC; kc++) {
#pragma unroll
                for (int j = 0; j < OPT; j++) {
                    float4 hj = h4s[w][kc][lane * OPT + j];
                    float pd = hj.x * mv[j][kc][0] + hj.y * mv[j][kc][1] + hj.z * mv[j][kc][2];
                    if (pd > best[j]) {   // first max wins (k ascending)
                        best[j] = pd;
                        bh[j][0] = hj.x; bh[j][1] = hj.y; bh[j][2] = hj.z;
                    }
                }
            }
        }
        __syncwarp();
    }

    if (act) {
#pragma unroll
        for (int j = 0; j < OPT; j++) {
            int o = lane * OPT + j;
            if (o < O) {
                float* op = out + (((size_t)b * O + o) * 3) * NN + n;
                op[0]      = bh[j][0];
                op[NN]     = bh[j][1];
                op[2 * NN] = bh[j][2];
            }
        }
    }
}

// ---------------- layer 5: vn_leaky on concat(x1..x4) -> (B,1023,N) ----------------
__global__ void __launch_bounds__(352) layer5_kernel(const float* __restrict__ Wd5) {
    constexpr int NP = 4;
    __shared__ float4 es[NP][169];
    __shared__ float dvs[NP][4];

    int b = blockIdx.x / (NN / NP);
    int tile = blockIdx.x % (NN / NP);
    int t = threadIdx.x;

    for (int idx = t; idx < NP * 169; idx += 352) {
        int p = idx / 169, c = idx - p * 169;
        int n = tile * NP + p;
        const float* src; int cc, CL;
        if (c < 21)      { src = d_x1; cc = c;      CL = 21; }
        else if (c < 42) { src = d_x2; cc = c - 21; CL = 21; }
        else if (c < 84) { src = d_x3; cc = c - 42; CL = 42; }
        else             { src = d_x4; cc = c - 84; CL = 85; }
        size_t base = (((size_t)b * CL + cc) * 3) * NN + n;
        es[p][c] = make_float4(src[base], src[base + NN], src[base + 2 * NN], 0.f);
    }
    __syncthreads();

    if (t < NP) {
        int p = t;
        float s0 = 0.f, s1 = 0.f, s2 = 0.f;
        for (int c = 0; c < 169; c++) {
            float wv = Wd5[c];
            float4 e = es[p][c];
            s0 += wv * e.x; s1 += wv * e.y; s2 += wv * e.z;
        }
        dvs[p][0] = s0; dvs[p][1] = s1; dvs[p][2] = s2;
        dvs[p][3] = 0.8f / (s0 * s0 + s1 * s1 + s2 * s2 + 1e-6f);
    }
    __syncthreads();

    int o = t;
    if (o < 341) {
        float a[NP][3];
#pragma unroll
        for (int p = 0; p < NP; p++) a[p][0] = a[p][1] = a[p][2] = 0.f;
        const float* wc = d_wp5t + o;
#pragma unroll 2
        for (int c = 0; c < 169; c++) {
            float wv = wc[(size_t)c * 341];
#pragma unroll
            for (int p = 0; p < NP; p++) {
                float4 e = es[p][c];
                a[p][0] += wv * e.x; a[p][1] += wv * e.y; a[p][2] += wv * e.z;
            }
        }
#pragma unroll
        for (int p = 0; p < NP; p++) {
            int n = tile * NP + p;
            float dot = a[p][0] * dvs[p][0] + a[p][1] * dvs[p][1] + a[p][2] * dvs[p][2];
            float h0, h1, h2;
            if (dot >= 0.f) { h0 = a[p][0]; h1 = a[p][1]; h2 = a[p][2]; }
            else {
                float cth = dot * dvs[p][3];
                h0 = a[p][0] - cth * dvs[p][0];
                h1 = a[p][1] - cth * dvs[p][1];
                h2 = a[p][2] - cth * dvs[p][2];
            }
            size_t base = ((size_t)b * 1023 + o * 3) * NN + n;
            d_h5[base]          = h0;
            d_h5[base + NN]     = h1;
            d_h5[base + 2 * NN] = h2;
        }
    }
}

// ---------------- global max + mean over N ----------------
__global__ void reduce_kernel() {
    int b = blockIdx.x / 1023;
    int ch = blockIdx.x - b * 1023;
    const float* row = d_h5 + (size_t)b * 1023 * NN + (size_t)ch * NN;
    int t = threadIdx.x;
    float mx = -CUDART_INF_F, sm = 0.f;
    for (int m = t; m < NN; m += 128) {
        float v = row[m];
        mx = fmaxf(mx, v);
        sm += v;
    }
    __shared__ float smx[128], ssm[128];
    smx[t] = mx; ssm[t] = sm;
    __syncthreads();
    for (int s = 64; s > 0; s >>= 1) {
        if (t < s) { smx[t] = fmaxf(smx[t], smx[t + s]); ssm[t] += ssm[t + s]; }
        __syncthreads();
    }
    if (t == 0) {
        d_g[b * 2046 + ch]        = smx[0];
        d_g[b * 2046 + 1023 + ch] = ssm[0] * (1.f / NN);
    }
}

// ---------------- FC: one warp per output element ----------------
__global__ void fc_kernel(const float* __restrict__ in, const float* __restrict__ W,
                          const float* __restrict__ bias, float* __restrict__ out,
                          int rows, int icols, int ocols, float slope) {
    int gw = (blockIdx.x * blockDim.x + threadIdx.x) >> 5;
    int lane = threadIdx.x & 31;
    if (gw >= rows * ocols) return;
    int r = gw / ocols;
    int o = gw - r * ocols;
    const float* ir = in + (size_t)r * icols;
    const float* wr = W + (size_t)o * icols;
    float s = 0.f;
    for (int c = lane; c < icols; c += 32) s += ir[c] * wr[c];
#pragma unroll
    for (int off = 16; off; off >>= 1) s += __shfl_down_sync(0xffffffffu, s, off);
    if (lane == 0) {
        s += bias[o];
        if (slope != 1.0f) s = (s >= 0.f) ? s : slope * s;
        out[(size_t)r * ocols + o] = s;
    }
}

// ---------------- launch ----------------
extern "C" void kernel_launch(void* const* d_in, const int* in_sizes, int n_in,
                              void* d_out, int out_size) {
    const float* x   = (const float*)d_in[0];
    const float* Wp1 = (const float*)d_in[1];
    const float* Wd1 = (const float*)d_in[2];
    const float* Wm1 = (const float*)d_in[3];
    const float* Wp2 = (const float*)d_in[4];
    const float* Wd2 = (const float*)d_in[5];
    const float* Wm2 = (const float*)d_in[6];
    const float* Wp3 = (const float*)d_in[7];
    const float* Wd3 = (const float*)d_in[8];
    const float* Wm3 = (const float*)d_in[9];
    const float* Wp4 = (const float*)d_in[10];
    const float* Wd4 = (const float*)d_in[11];
    const float* Wm4 = (const float*)d_in[12];
    const float* Wp5 = (const float*)d_in[13];
    const float* Wd5 = (const float*)d_in[14];
    const float* W1  = (const float*)d_in[15];
    const float* b1  = (const float*)d_in[16];
    const float* W2  = (const float*)d_in[17];
    const float* b2  = (const float*)d_in[18];
    const float* W3  = (const float*)d_in[19];
    const float* b3  = (const float*)d_in[20];

    float *f0, *x1, *x2, *x3, *x4, *pad, *ctrb, *g, *g1, *g2;
    cudaGetSymbolAddress((void**)&f0,   d_f0);
    cudaGetSymbolAddress((void**)&x1,   d_x1);
    cudaGetSymbolAddress((void**)&x2,   d_x2);
    cudaGetSymbolAddress((void**)&x3,   d_x3);
    cudaGetSymbolAddress((void**)&x4,   d_x4);
    cudaGetSymbolAddress((void**)&pad,  d_pad);
    cudaGetSymbolAddress((void**)&ctrb, d_ctr);
    cudaGetSymbolAddress((void**)&g,    d_g);
    cudaGetSymbolAddress((void**)&g1,   d_g1);
    cudaGetSymbolAddress((void**)&g2,   d_g2);

    // dynamic smem sizes for single-pass gemm_pd (4 weight arrays of O*Cp floats)
    const int sm1 = 4 * 21 * 2  * 4;
    const int sm2 = 4 * 21 * 22 * 4;
    const int sm3 = 4 * 42 * 22 * 4;
    const int sm4 = 4 * 85 * 42 * 4;   // 57120 B > 48KB: needs opt-in
    cudaFuncSetAttribute(gemm_pd<42, 85>, cudaFuncAttributeMaxDynamicSharedMemorySize, sm4);

    transpose_kernel<<<(BB * NN * 3 + 255) / 256, 256>>>(x);
    transpose_w5<<<(341 * 169 + 255) / 256, 256>>>(Wp5);

    sq_kernel<3><<<BB * NN / 256, 256>>>(f0);
    knn_kernel<3><<<BB * NN / 4, 256>>>(f0);
    gemm_pd<1, 21><<<BB * (NN / 32), 96, sm1>>>(f0, Wp1, Wd1, pad, ctrb);
    edge_combine<21, 1, 4><<<BB * NN / 4, 128>>>(pad, ctrb, Wm1, x1);

    sq_kernel<63><<<BB * NN / 256, 256>>>(x1);
    knn_kernel<63><<<BB * NN / 4, 256>>>(x1);
    gemm_pd<21, 21><<<BB * (NN / 32), 96, sm2>>>(x1, Wp2, Wd2, pad, ctrb);
    edge_combine<21, 1, 4><<<BB * NN / 4, 128>>>(pad, ctrb, Wm2, x2);

    sq_kernel<63><<<BB * NN / 256, 256>>>(x2);
    knn_kernel<63><<<BB * NN / 4, 256>>>(x2);
    gemm_pd<21, 42><<<BB * (NN / 32), 96, sm3>>>(x2, Wp3, Wd3, pad, ctrb);
    edge_combine<42, 2, 4><<<BB * NN / 4, 128>>>(pad, ctrb, Wm3, x3);

    sq_kernel<126><<<BB * NN / 256, 256>>>(x3);
    knn_kernel<126><<<BB * NN / 4, 256>>>(x3);
    gemm_pd<42, 85><<<BB * (NN / 32), 96, sm4>>>(x3, Wp4, Wd4, pad, ctrb);
    edge_combine<85, 3, 2><<<BB * NN / 2, 64>>>(pad, ctrb, Wm4, x4);

    layer5_kernel<<<BB * NN / 4, 352>>>(Wd5);
    reduce_kernel<<<BB * 1023, 128>>>();

    fc_kernel<<<(8 * 512 * 32 + 255) / 256, 256>>>(g,  W1, b1, g1, 8, 2046, 512, 0.01f);
    fc_kernel<<<(8 * 256 * 32 + 255) / 256, 256>>>(g1, W2, b2, g2, 8, 512,  256, 0.01f);
    fc_kernel<<<(8 * 128 * 32 + 255) / 256, 256>>>(g2, W3, b3, (float*)d_out, 8, 256, 128, 1.0f);
}

// round 8
// speedup vs baseline: 4.9861x; 1.0240x over previous
#include <cuda_runtime.h>
#include <math_constants.h>

#define BB 8
#define NN 1024
#define KK 20

typedef unsigned long long ull;

// ---------------- scratch (device globals: no allocation allowed) ----------------
__device__ float d_f0[BB * 3 * NN];            // (B,3,N)
__device__ float d_x1[BB * 21 * 3 * NN];
__device__ float d_x2[BB * 21 * 3 * NN];
__device__ float d_x3[BB * 42 * 3 * NN];
__device__ float d_x4[BB * 85 * 3 * NN];
__device__ int   d_knnIdx[BB * NN * KK];
__device__ float d_sqm[BB * NN];
__device__ float d_pad[BB * NN * 85 * 8 + 16];  // per-point, layout (B,N,O,8): [pa0,da0,pa1,da1,pa2,da2,-,-]
__device__ float d_ctr[BB * NN * 85 * 8 + 16];  // per-point (pb,db) same layout
__device__ float4 d_w4[4998];                   // interleaved [ap,bp,ad,bd] for layers 1..4
__device__ float d_wp5t[169 * 341];
__device__ float d_h5[BB * 1023 * NN];
__device__ float d_g [BB * 2046];
__device__ float d_g1[BB * 512];
__device__ float d_g2[BB * 256];

// ---------------- transpose x (B,N,3) -> f0 (B,3,N) ----------------
__global__ void transpose_kernel(const float* __restrict__ x) {
    int i = blockIdx.x * blockDim.x + threadIdx.x;
    if (i >= BB * NN * 3) return;
    int b = i / (NN * 3);
    int r = i - b * (NN * 3);
    int n = r / 3;
    int j = r - n * 3;
    d_f0[((size_t)b * 3 + j) * NN + n] = x[i];
}

// ---------------- transpose Wp5 (341,169) -> (169,341) ----------------
__global__ void transpose_w5(const float* __restrict__ Wp5) {
    int i = blockIdx.x * blockDim.x + threadIdx.x;
    if (i >= 341 * 169) return;
    int o = i / 169, c = i - o * 169;
    d_wp5t[c * 341 + o] = Wp5[i];
}

// ---------------- build interleaved weight table for all 4 edge layers ----------------
// layout per layer: idx = off + o*Cp + c -> float4(ap=Wl_p, bp=Wr_p-Wl_p, ad=Wl_d, bd=Wr_d-Wl_d)
// offsets: L1 [0,42) Cp=2 ; L2 [42,504) Cp=22 ; L3 [504,1428) Cp=22 ; L4 [1428,4998) Cp=42
__global__ void w4_prep(const float* __restrict__ Wp1, const float* __restrict__ Wd1,
                        const float* __restrict__ Wp2, const float* __restrict__ Wd2,
                        const float* __restrict__ Wp3, const float* __restrict__ Wd3,
                        const float* __restrict__ Wp4, const float* __restrict__ Wd4) {
    int i = blockIdx.x * 256 + threadIdx.x;
    if (i >= 4998) return;
    const float *Wp, *Wd; int C, Cp, rel;
    if (i < 42)        { Wp = Wp1; Wd = Wd1; C = 1;  Cp = 2;  rel = i; }
    else if (i < 504)  { Wp = Wp2; Wd = Wd2; C = 21; Cp = 22; rel = i - 42; }
    else if (i < 1428) { Wp = Wp3; Wd = Wd3; C = 21; Cp = 22; rel = i - 504; }
    else               { Wp = Wp4; Wd = Wd4; C = 42; Cp = 42; rel = i - 1428; }
    int o = rel / Cp, c = rel - o * Cp;
    float ap = 0.f, bp = 0.f, ad = 0.f, bd = 0.f;
    if (c < C) {
        float wl = Wp[o * 2 * C + c], wr = Wp[o * 2 * C + C + c];
        ap = wl; bp = wr - wl;
        wl = Wd[o * 2 * C + c]; wr = Wd[o * 2 * C + C + c];
        ad = wl; bd = wr - wl;
    }
    d_w4[i] = make_float4(ap, bp, ad, bd);
}

// ---------------- per-point squared norms (same d-ascending FFMA chain as before) ----------------
template <int D>
__global__ void __launch_bounds__(256) sq_kernel(const float* __restrict__ feat) {
    int i = blockIdx.x * 256 + threadIdx.x;
    int b = i >> 10, m = i & (NN - 1);
    const float* f = feat + (size_t)b * D * NN + m;
    float s = 0.f;
#pragma unroll 4
    for (int d = 0; d < D; d++) { float v = f[(size_t)d * NN]; s += v * v; }
    d_sqm[i] = s;
}

// ---------------- KNN: block (256 thr) per 4 rows; REDUX-based selection ----------------
template <int D>
__global__ void __launch_bounds__(256) knn_kernel(const float* __restrict__ feat) {
    constexpr int NB = 4;
    int b = blockIdx.x / (NN / NB);
    int tile = blockIdx.x % (NN / NB);
    const float* f = feat + (size_t)b * D * NN;

    __shared__ float4   ctr4[D];        // [d] -> centers of rows 0..3
    __shared__ unsigned wmaxs[NB][8];
    __shared__ unsigned winkey[NB];
    __shared__ int      winwarp[NB];

    int t = threadIdx.x, lane = t & 31, wid = t >> 5;
    int nb0 = tile * NB;

    for (int d = t; d < D; d += 256)
        ctr4[d] = make_float4(f[(size_t)d * NN + nb0],     f[(size_t)d * NN + nb0 + 1],
                              f[(size_t)d * NN + nb0 + 2], f[(size_t)d * NN + nb0 + 3]);
    __syncthreads();

    float sqn[NB];
#pragma unroll
    for (int r = 0; r < NB; r++) sqn[r] = d_sqm[b * NN + nb0 + r];
    float4 sq4 = *(const float4*)&d_sqm[b * NN + 4 * t];

    float acc[NB][4];
#pragma unroll
    for (int r = 0; r < NB; r++)
#pragma unroll
        for (int j = 0; j < 4; j++) acc[r][j] = 0.f;

    const float4* fp = (const float4*)(f) + t;   // element 4t of row 0
    for (int d = 0; d < D; d++) {
        float4 v = fp[(size_t)d * (NN / 4)];
        float4 c = ctr4[d];
        acc[0][0] += c.x * v.x; acc[0][1] += c.x * v.y; acc[0][2] += c.x * v.z; acc[0][3] += c.x * v.w;
        acc[1][0] += c.y * v.x; acc[1][1] += c.y * v.y; acc[1][2] += c.y * v.z; acc[1][3] += c.y * v.w;
        acc[2][0] += c.z * v.x; acc[2][1] += c.z * v.y; acc[2][2] += c.z * v.z; acc[2][3] += c.z * v.w;
        acc[3][0] += c.w * v.x; acc[3][1] += c.w * v.y; acc[3][2] += c.w * v.z; acc[3][3] += c.w * v.w;
    }

    // packed candidates: (monotone key << 10) | (1023 - m); sorted desc per row (5-CAS network)
    ull cand[NB][4];
#pragma unroll
    for (int r = 0; r < NB; r++) {
        float sqj[4] = { sq4.x, sq4.y, sq4.z, sq4.w };
#pragma unroll
        for (int j = 0; j < 4; j++) {
            float dv = 2.f * acc[r][j] - sqn[r] - sqj[j];
            unsigned bits = __float_as_uint(dv);
            unsigned key = (bits & 0x80000000u) ? ~bits : (bits | 0x80000000u);
            int m = 4 * t + j;
            cand[r][j] = ((ull)key << 10) | (unsigned)(1023 - m);
        }
        ull c0 = cand[r][0], c1 = cand[r][1], c2 = cand[r][2], c3 = cand[r][3], tmp;
        if (c1 > c0) { tmp = c0; c0 = c1; c1 = tmp; }
        if (c3 > c2) { tmp = c2; c2 = c3; c3 = tmp; }
        if (c2 > c0) { tmp = c0; c0 = c2; c2 = tmp; }
        if (c3 > c1) { tmp = c1; c1 = c3; c3 = tmp; }
        if (c2 > c1) { tmp = c1; c1 = c2; c2 = tmp; }
        cand[r][0] = c0; cand[r][1] = c1; cand[r][2] = c2; cand[r][3] = c3;
    }
    int ptr[NB] = {0, 0, 0, 0};

    size_t obase = ((size_t)b * NN + nb0) * KK;
    for (int k = 0; k < KK; k++) {
        unsigned hk[NB];
#pragma unroll
        for (int r = 0; r < NB; r++) {
            int p = ptr[r];
            ull h = (p <= 1) ? ((p == 0) ? cand[r][0] : cand[r][1])
                             : ((p == 2) ? cand[r][2] : ((p == 3) ? cand[r][3] : 0ULL));
            hk[r] = (unsigned)(h >> 10);
            unsigned wm = __reduce_max_sync(0xffffffffu, hk[r]);
            if (lane == 0) wmaxs[r][wid] = wm;
        }
        __syncthreads();
        if (wid == 0) {
            int r = lane >> 3;
            unsigned v = wmaxs[r][lane & 7];
            unsigned gmask = 0xffu << (r * 8);
            unsigned gm = __reduce_max_sync(gmask, v);
            unsigned bal = __ballot_sync(gmask, v == gm);
            if (lane == __ffs(bal) - 1) { winkey[r] = gm; winwarp[r] = lane & 7; }
        }
        __syncthreads();
#pragma unroll
        for (int r = 0; r < NB; r++) {
            if (wid == winwarp[r]) {
                unsigned gm = winkey[r];
                unsigned bal = __ballot_sync(0xffffffffu, hk[r] == gm);
                if (lane == __ffs(bal) - 1) {
                    int p = ptr[r];
                    ull h = (p <= 1) ? ((p == 0) ? cand[r][0] : cand[r][1])
                                     : ((p == 2) ? cand[r][2] : cand[r][3]);
                    d_knnIdx[obase + r * KK + k] = 1023 - (int)(h & 1023ULL);
                    ptr[r] = p + 1;
                }
            }
        }
        __syncthreads();
    }
}

// ---------------- per-point GEMM v2: no smem, uniform LDG.128 weights, o-split ----------------
// Output pad/ctr layout: (B,N,O,8): per o: [p0,d0,p1,d1,p2,d2,-,-]  (identical to R7)
template <int C, int O, int OG, int WOFF>
__global__ void __launch_bounds__(96) gemm2(const float* __restrict__ x,
                                            float* __restrict__ pad,
                                            float* __restrict__ ctrb) {
    constexpr int Cp = (C + 1) & ~1;
    constexpr int OC = (O + OG - 1) / OG;
    int b = blockIdx.x / (NN / 32);
    int tile = blockIdx.x % (NN / 32);
    int og = blockIdx.y;
    int t = threadIdx.x;
    int n = tile * 32 + (t & 31);
    int ax = t >> 5;

    float xr[Cp];
#pragma unroll
    for (int c = 0; c < C; c++)
        xr[c] = x[(((size_t)b * C + c) * 3 + ax) * NN + n];
    if (Cp > C) xr[Cp - 1] = 0.f;

    int o0 = og * OC;
    int o1 = (o0 + OC < O) ? o0 + OC : O;
    const float4* W4 = d_w4 + WOFF;
    size_t obase = (size_t)(b * NN + n) * (O * 8) + ax * 2;

    for (int o = o0; o < o1; o++) {
        float pa = 0.f, pb = 0.f, da = 0.f, db = 0.f;
#pragma unroll
        for (int cc = 0; cc < Cp; cc += 2) {
            float4 w0 = W4[o * Cp + cc];
            float4 w1 = W4[o * Cp + cc + 1];
            float x0 = xr[cc], x1v = xr[cc + 1];
            pa += w0.x * x0 + w1.x * x1v;
            pb += w0.y * x0 + w1.y * x1v;
            da += w0.z * x0 + w1.z * x1v;
            db += w0.w * x0 + w1.w * x1v;
        }
        *(float2*)&pad[obase + o * 8]  = make_float2(pa, da);
        *(float2*)&ctrb[obase + o * 8] = make_float2(pb, db);
    }
}

// ---------------- edge combine + leaky + learned max-pool (KC=4 neighbor chunking) ----------------
template <int O, int OPT, int NP>
__global__ void __launch_bounds__(32 * NP) edge_combine(const float* __restrict__ pad,
                                                        const float* __restrict__ ctrb,
                                                        const float* __restrict__ Wm,
                                                        float* __restrict__ out) {
    constexpr int AT = (O + OPT - 1) / OPT;   // active lanes
    constexpr int Opad = AT * OPT;
    constexpr int KC = 4;
    constexpr int T = 32 * NP;

    __shared__ float  WmT[O * Opad];
    __shared__ float4 h4s[NP][KC][Opad];
    __shared__ int    kk[NP][KK];

    int b = blockIdx.x / (NN / NP);
    int ptile = blockIdx.x % (NN / NP);
    int t = threadIdx.x;
    int w = t >> 5, lane = t & 31;

    for (int i = t; i < O * O; i += T) {
        int o = i / O, c = i - o * O;
        WmT[c * Opad + o] = Wm[i];
    }
    if constexpr (Opad > O) {
        for (int i = t; i < O * (Opad - O); i += T) {
            int c = i / (Opad - O), j = i - c * (Opad - O);
            WmT[c * Opad + O + j] = 0.f;
        }
    }
    int n = ptile * NP + w;
    if (lane < KK) kk[w][lane] = d_knnIdx[((size_t)b * NN + n) * KK + lane];
    __syncthreads();

    bool act = lane < AT;
    float pb[OPT][3], db[OPT][3];
    size_t cbase = (size_t)(b * NN + n) * (O * 8);
    if (act) {
#pragma unroll
        for (int j = 0; j < OPT; j++) {
            int o = lane * OPT + j;
            float4 u  = *(const float4*)&ctrb[cbase + o * 8];
            float2 u2 = *(const float2*)&ctrb[cbase + o * 8 + 4];
            pb[j][0] = u.x;  db[j][0] = u.y;
            pb[j][1] = u.z;  db[j][1] = u.w;
            pb[j][2] = u2.x; db[j][2] = u2.y;
        }
    }

    float best[OPT];
    float bh[OPT][3];
#pragma unroll
    for (int j = 0; j < OPT; j++) { best[j] = -CUDART_INF_F; bh[j][0] = bh[j][1] = bh[j][2] = 0.f; }

    for (int chunk = 0; chunk < KK / KC; chunk++) {
#pragma unroll
        for (int kc = 0; kc < KC; kc++) {
            int m = kk[w][chunk * KC + kc];
            if (act) {
                size_t gbase = (size_t)(b * NN + m) * (O * 8);
#pragma unroll
                for (int j = 0; j < OPT; j++) {
                    int o = lane * OPT + j;
                    float4 u  = *(const float4*)&pad[gbase + o * 8];
                    float2 u2 = *(const float2*)&pad[gbase + o * 8 + 4];
                    float p0 = u.x  + pb[j][0], q0 = u.y  + db[j][0];
                    float p1 = u.z  + pb[j][1], q1 = u.w  + db[j][1];
                    float p2 = u2.x + pb[j][2], q2 = u2.y + db[j][2];
                    float dot = p0 * q0 + p1 * q1 + p2 * q2;
                    float h0, h1, h2;
                    if (dot >= 0.f) {
                        h0 = p0; h1 = p1; h2 = p2;
                    } else {
                        float dsq = q0 * q0 + q1 * q1 + q2 * q2;
                        float cth = 0.8f * dot / (dsq + 1e-6f);
                        h0 = p0 - cth * q0; h1 = p1 - cth * q1; h2 = p2 - cth * q2;
                    }
                    h4s[w][kc][lane * OPT + j] = make_float4(h0, h1, h2, 0.f);
                }
            }
        }
        __syncwarp();
        if (act) {
            float mv[OPT][KC][3];
#pragma unroll
            for (int j = 0; j < OPT; j++)
#pragma unroll
                for (int kc = 0; kc < KC; kc++) mv[j][kc][0] = mv[j][kc][1] = mv[j][kc][2] = 0.f;
#pragma unroll 2
            for (int c = 0; c < O; c++) {
                float wv[OPT];
#pragma unroll
                for (int j = 0; j < OPT; j++) wv[j] = WmT[c * Opad + lane * OPT + j];
#pragma unroll
                for (int kc = 0; kc < KC; kc++) {
                    float4 hc = h4s[w][kc][c];
#pragma unroll
                    for (int j = 0; j < OPT; j++) {
                        mv[j][kc][0] += wv[j] * hc.x;
                        mv[j][kc][1] += wv[j] * hc.y;
                        mv[j][kc][2] += wv[j] * hc.z;
                    }
                }
            }
#pragma unroll
            for (int kc = 0; kc < KC; kc++) {
#pragma unroll
                for (int j = 0; j < OPT; j++) {
                    float4 hj = h4s[w][kc][lane * OPT + j];
                    float pd = hj.x * mv[j][kc][0] + hj.y * mv[j][kc][1] + hj.z * mv[j][kc][2];
                    if (pd > best[j]) {   // first max wins (k ascending)
                        best[j] = pd;
                        bh[j][0] = hj.x; bh[j][1] = hj.y; bh[j][2] = hj.z;
                    }
                }
            }
        }
        __syncwarp();
    }

    if (act) {
#pragma unroll
        for (int j = 0; j < OPT; j++) {
            int o = lane * OPT + j;
            if (o < O) {
                float* op = out + (((size_t)b * O + o) * 3) * NN + n;
                op[0]      = bh[j][0];
                op[NN]     = bh[j][1];
                op[2 * NN] = bh[j][2];
            }
        }
    }
}

// ---------------- layer 5: vn_leaky on concat(x1..x4) -> (B,1023,N) ----------------
__global__ void __launch_bounds__(352) layer5_kernel(const float* __restrict__ Wd5) {
    constexpr int NP = 4;
    __shared__ float4 es[NP][169];
    __shared__ float dvs[NP][4];

    int b = blockIdx.x / (NN / NP);
    int tile = blockIdx.x % (NN / NP);
    int t = threadIdx.x;

    for (int idx = t; idx < NP * 169; idx += 352) {
        int p = idx / 169, c = idx - p * 169;
        int n = tile * NP + p;
        const float* src; int cc, CL;
        if (c < 21)      { src = d_x1; cc = c;      CL = 21; }
        else if (c < 42) { src = d_x2; cc = c - 21; CL = 21; }
        else if (c < 84) { src = d_x3; cc = c - 42; CL = 42; }
        else             { src = d_x4; cc = c - 84; CL = 85; }
        size_t base = (((size_t)b * CL + cc) * 3) * NN + n;
        es[p][c] = make_float4(src[base], src[base + NN], src[base + 2 * NN], 0.f);
    }
    __syncthreads();

    if (t < NP) {
        int p = t;
        float s0 = 0.f, s1 = 0.f, s2 = 0.f;
        for (int c = 0; c < 169; c++) {
            float wv = Wd5[c];
            float4 e = es[p][c];
            s0 += wv * e.x; s1 += wv * e.y; s2 += wv * e.z;
        }
        dvs[p][0] = s0; dvs[p][1] = s1; dvs[p][2] = s2;
        dvs[p][3] = 0.8f / (s0 * s0 + s1 * s1 + s2 * s2 + 1e-6f);
    }
    __syncthreads();

    int o = t;
    if (o < 341) {
        float a[NP][3];
#pragma unroll
        for (int p = 0; p < NP; p++) a[p][0] = a[p][1] = a[p][2] = 0.f;
        const float* wc = d_wp5t + o;
#pragma unroll 2
        for (int c = 0; c < 169; c++) {
            float wv = wc[(size_t)c * 341];
#pragma unroll
            for (int p = 0; p < NP; p++) {
                float4 e = es[p][c];
                a[p][0] += wv * e.x; a[p][1] += wv * e.y; a[p][2] += wv * e.z;
            }
        }
#pragma unroll
        for (int p = 0; p < NP; p++) {
            int n = tile * NP + p;
            float dot = a[p][0] * dvs[p][0] + a[p][1] * dvs[p][1] + a[p][2] * dvs[p][2];
            float h0, h1, h2;
            if (dot >= 0.f) { h0 = a[p][0]; h1 = a[p][1]; h2 = a[p][2]; }
            else {
                float cth = dot * dvs[p][3];
                h0 = a[p][0] - cth * dvs[p][0];
                h1 = a[p][1] - cth * dvs[p][1];
                h2 = a[p][2] - cth * dvs[p][2];
            }
            size_t base = ((size_t)b * 1023 + o * 3) * NN + n;
            d_h5[base]          = h0;
            d_h5[base + NN]     = h1;
            d_h5[base + 2 * NN] = h2;
        }
    }
}

// ---------------- global max + mean over N ----------------
__global__ void reduce_kernel() {
    int b = blockIdx.x / 1023;
    int ch = blockIdx.x - b * 1023;
    const float* row = d_h5 + (size_t)b * 1023 * NN + (size_t)ch * NN;
    int t = threadIdx.x;
    float mx = -CUDART_INF_F, sm = 0.f;
    for (int m = t; m < NN; m += 128) {
        float v = row[m];
        mx = fmaxf(mx, v);
        sm += v;
    }
    __shared__ float smx[128], ssm[128];
    smx[t] = mx; ssm[t] = sm;
    __syncthreads();
    for (int s = 64; s > 0; s >>= 1) {
        if (t < s) { smx[t] = fmaxf(smx[t], smx[t + s]); ssm[t] += ssm[t + s]; }
        __syncthreads();
    }
    if (t == 0) {
        d_g[b * 2046 + ch]        = smx[0];
        d_g[b * 2046 + 1023 + ch] = ssm[0] * (1.f / NN);
    }
}

// ---------------- FC: one warp per output element ----------------
__global__ void fc_kernel(const float* __restrict__ in, const float* __restrict__ W,
                          const float* __restrict__ bias, float* __restrict__ out,
                          int rows, int icols, int ocols, float slope) {
    int gw = (blockIdx.x * blockDim.x + threadIdx.x) >> 5;
    int lane = threadIdx.x & 31;
    if (gw >= rows * ocols) return;
    int r = gw / ocols;
    int o = gw - r * ocols;
    const float* ir = in + (size_t)r * icols;
    const float* wr = W + (size_t)o * icols;
    float s = 0.f;
    for (int c = lane; c < icols; c += 32) s += ir[c] * wr[c];
#pragma unroll
    for (int off = 16; off; off >>= 1) s += __shfl_down_sync(0xffffffffu, s, off);
    if (lane == 0) {
        s += bias[o];
        if (slope != 1.0f) s = (s >= 0.f) ? s : slope * s;
        out[(size_t)r * ocols + o] = s;
    }
}

// ---------------- launch ----------------
extern "C" void kernel_launch(void* const* d_in, const int* in_sizes, int n_in,
                              void* d_out, int out_size) {
    const float* x   = (const float*)d_in[0];
    const float* Wp1 = (const float*)d_in[1];
    const float* Wd1 = (const float*)d_in[2];
    const float* Wm1 = (const float*)d_in[3];
    const float* Wp2 = (const float*)d_in[4];
    const float* Wd2 = (const float*)d_in[5];
    const float* Wm2 = (const float*)d_in[6];
    const float* Wp3 = (const float*)d_in[7];
    const float* Wd3 = (const float*)d_in[8];
    const float* Wm3 = (const float*)d_in[9];
    const float* Wp4 = (const float*)d_in[10];
    const float* Wd4 = (const float*)d_in[11];
    const float* Wm4 = (const float*)d_in[12];
    const float* Wp5 = (const float*)d_in[13];
    const float* Wd5 = (const float*)d_in[14];
    const float* W1  = (const float*)d_in[15];
    const float* b1  = (const float*)d_in[16];
    const float* W2  = (const float*)d_in[17];
    const float* b2  = (const float*)d_in[18];
    const float* W3  = (const float*)d_in[19];
    const float* b3  = (const float*)d_in[20];

    float *f0, *x1, *x2, *x3, *x4, *pad, *ctrb, *g, *g1, *g2;
    cudaGetSymbolAddress((void**)&f0,   d_f0);
    cudaGetSymbolAddress((void**)&x1,   d_x1);
    cudaGetSymbolAddress((void**)&x2,   d_x2);
    cudaGetSymbolAddress((void**)&x3,   d_x3);
    cudaGetSymbolAddress((void**)&x4,   d_x4);
    cudaGetSymbolAddress((void**)&pad,  d_pad);
    cudaGetSymbolAddress((void**)&ctrb, d_ctr);
    cudaGetSymbolAddress((void**)&g,    d_g);
    cudaGetSymbolAddress((void**)&g1,   d_g1);
    cudaGetSymbolAddress((void**)&g2,   d_g2);

    transpose_kernel<<<(BB * NN * 3 + 255) / 256, 256>>>(x);
    transpose_w5<<<(341 * 169 + 255) / 256, 256>>>(Wp5);
    w4_prep<<<(4998 + 255) / 256, 256>>>(Wp1, Wd1, Wp2, Wd2, Wp3, Wd3, Wp4, Wd4);

    sq_kernel<3><<<BB * NN / 256, 256>>>(f0);
    knn_kernel<3><<<BB * NN / 4, 256>>>(f0);
    gemm2<1, 21, 2, 0><<<dim3(BB * (NN / 32), 2), 96>>>(f0, pad, ctrb);
    edge_combine<21, 1, 4><<<BB * NN / 4, 128>>>(pad, ctrb, Wm1, x1);

    sq_kernel<63><<<BB * NN / 256, 256>>>(x1);
    knn_kernel<63><<<BB * NN / 4, 256>>>(x1);
    gemm2<21, 21, 2, 42><<<dim3(BB * (NN / 32), 2), 96>>>(x1, pad, ctrb);
    edge_combine<21, 1, 4><<<BB * NN / 4, 128>>>(pad, ctrb, Wm2, x2);

    sq_kernel<63><<<BB * NN / 256, 256>>>(x2);
    knn_kernel<63><<<BB * NN / 4, 256>>>(x2);
    gemm2<21, 42, 2, 504><<<dim3(BB * (NN / 32), 2), 96>>>(x2, pad, ctrb);
    edge_combine<42, 2, 4><<<BB * NN / 4, 128>>>(pad, ctrb, Wm3, x3);

    sq_kernel<126><<<BB * NN / 256, 256>>>(x3);
    knn_kernel<126><<<BB * NN / 4, 256>>>(x3);
    gemm2<42, 85, 4, 1428><<<dim3(BB * (NN / 32), 4), 96>>>(x3, pad, ctrb);
    edge_combine<85, 3, 2><<<BB * NN / 2, 64>>>(pad, ctrb, Wm4, x4);

    layer5_kernel<<<BB * NN / 4, 352>>>(Wd5);
    reduce_kernel<<<BB * 1023, 128>>>();

    fc_kernel<<<(8 * 512 * 32 + 255) / 256, 256>>>(g,  W1, b1, g1, 8, 2046, 512, 0.01f);
    fc_kernel<<<(8 * 256 * 32 + 255) / 256, 256>>>(g1, W2, b2, g2, 8, 512,  256, 0.01f);
    fc_kernel<<<(8 * 128 * 32 + 255) / 256, 256>>>(g2, W3, b3, (float*)d_out, 8, 256, 128, 1.0f);
}

// round 9
// speedup vs baseline: 5.6962x; 1.1424x over previous
#include <cuda_runtime.h>
#include <math_constants.h>

#define BB 8
#define NN 1024
#define KK 20

typedef unsigned long long ull;

// ---------------- scratch (device globals: no allocation allowed) ----------------
__device__ float d_f0[BB * 3 * NN];            // (B,3,N)
__device__ float d_x1[BB * 21 * 3 * NN];
__device__ float d_x2[BB * 21 * 3 * NN];
__device__ float d_x3[BB * 42 * 3 * NN];
__device__ float d_x4[BB * 85 * 3 * NN];
__device__ int   d_knnIdx[BB * NN * KK];
__device__ float d_sqm[BB * NN];
__device__ float d_pad[BB * NN * 85 * 8 + 16];  // per-point, layout (B,N,O,8): [pa0,da0,pa1,da1,pa2,da2,-,-]
__device__ float d_ctr[BB * NN * 85 * 8 + 16];  // per-point (pb,db) same layout
__device__ float4 d_w4[4998];                   // interleaved [ap,bp,ad,bd] for layers 1..4
__device__ float d_wp5t[169 * 341];
__device__ float d_h5[BB * 1023 * NN];
__device__ float d_g [BB * 2046];
__device__ float d_g1[BB * 512];
__device__ float d_g2[BB * 256];

// ---------------- transpose x (B,N,3) -> f0 (B,3,N) ----------------
__global__ void transpose_kernel(const float* __restrict__ x) {
    int i = blockIdx.x * blockDim.x + threadIdx.x;
    if (i >= BB * NN * 3) return;
    int b = i / (NN * 3);
    int r = i - b * (NN * 3);
    int n = r / 3;
    int j = r - n * 3;
    d_f0[((size_t)b * 3 + j) * NN + n] = x[i];
}

// ---------------- transpose Wp5 (341,169) -> (169,341) ----------------
__global__ void transpose_w5(const float* __restrict__ Wp5) {
    int i = blockIdx.x * blockDim.x + threadIdx.x;
    if (i >= 341 * 169) return;
    int o = i / 169, c = i - o * 169;
    d_wp5t[c * 341 + o] = Wp5[i];
}

// ---------------- build interleaved weight table for all 4 edge layers ----------------
__global__ void w4_prep(const float* __restrict__ Wp1, const float* __restrict__ Wd1,
                        const float* __restrict__ Wp2, const float* __restrict__ Wd2,
                        const float* __restrict__ Wp3, const float* __restrict__ Wd3,
                        const float* __restrict__ Wp4, const float* __restrict__ Wd4) {
    int i = blockIdx.x * 256 + threadIdx.x;
    if (i >= 4998) return;
    const float *Wp, *Wd; int C, Cp, rel;
    if (i < 42)        { Wp = Wp1; Wd = Wd1; C = 1;  Cp = 2;  rel = i; }
    else if (i < 504)  { Wp = Wp2; Wd = Wd2; C = 21; Cp = 22; rel = i - 42; }
    else if (i < 1428) { Wp = Wp3; Wd = Wd3; C = 21; Cp = 22; rel = i - 504; }
    else               { Wp = Wp4; Wd = Wd4; C = 42; Cp = 42; rel = i - 1428; }
    int o = rel / Cp, c = rel - o * Cp;
    float ap = 0.f, bp = 0.f, ad = 0.f, bd = 0.f;
    if (c < C) {
        float wl = Wp[o * 2 * C + c], wr = Wp[o * 2 * C + C + c];
        ap = wl; bp = wr - wl;
        wl = Wd[o * 2 * C + c]; wr = Wd[o * 2 * C + C + c];
        ad = wl; bd = wr - wl;
    }
    d_w4[i] = make_float4(ap, bp, ad, bd);
}

// ---------------- per-point squared norms ----------------
template <int D>
__global__ void __launch_bounds__(256) sq_kernel(const float* __restrict__ feat) {
    int i = blockIdx.x * 256 + threadIdx.x;
    int b = i >> 10, m = i & (NN - 1);
    const float* f = feat + (size_t)b * D * NN + m;
    float s = 0.f;
#pragma unroll 4
    for (int d = 0; d < D; d++) { float v = f[(size_t)d * NN]; s += v * v; }
    d_sqm[i] = s;
}

// ---------------- KNN v3: warp-local top-20 then single merge (2 block syncs total) ----------------
template <int D>
__global__ void __launch_bounds__(256) knn_kernel(const float* __restrict__ feat) {
    constexpr int NB = 4;
    int b = blockIdx.x / (NN / NB);
    int tile = blockIdx.x % (NN / NB);
    const float* f = feat + (size_t)b * D * NN;

    __shared__ float4 ctr4[D];          // [d] -> centers of rows 0..3
    __shared__ ull    lists[NB][8 * KK];

    int t = threadIdx.x, lane = t & 31, wid = t >> 5;
    int nb0 = tile * NB;

    for (int d = t; d < D; d += 256)
        ctr4[d] = make_float4(f[(size_t)d * NN + nb0],     f[(size_t)d * NN + nb0 + 1],
                              f[(size_t)d * NN + nb0 + 2], f[(size_t)d * NN + nb0 + 3]);
    __syncthreads();

    float sqn[NB];
#pragma unroll
    for (int r = 0; r < NB; r++) sqn[r] = d_sqm[b * NN + nb0 + r];
    float4 sq4 = *(const float4*)&d_sqm[b * NN + 4 * t];

    float acc[NB][4];
#pragma unroll
    for (int r = 0; r < NB; r++)
#pragma unroll
        for (int j = 0; j < 4; j++) acc[r][j] = 0.f;

    const float4* fp = (const float4*)(f) + t;   // element 4t of row 0
    for (int d = 0; d < D; d++) {
        float4 v = fp[(size_t)d * (NN / 4)];
        float4 c = ctr4[d];
        acc[0][0] += c.x * v.x; acc[0][1] += c.x * v.y; acc[0][2] += c.x * v.z; acc[0][3] += c.x * v.w;
        acc[1][0] += c.y * v.x; acc[1][1] += c.y * v.y; acc[1][2] += c.y * v.z; acc[1][3] += c.y * v.w;
        acc[2][0] += c.z * v.x; acc[2][1] += c.z * v.y; acc[2][2] += c.z * v.z; acc[2][3] += c.z * v.w;
        acc[3][0] += c.w * v.x; acc[3][1] += c.w * v.y; acc[3][2] += c.w * v.z; acc[3][3] += c.w * v.w;
    }

    // packed candidates: (monotone key << 10) | (1023 - m); sorted desc per row (5-CAS network)
    ull cand[NB][4];
#pragma unroll
    for (int r = 0; r < NB; r++) {
        float sqj[4] = { sq4.x, sq4.y, sq4.z, sq4.w };
#pragma unroll
        for (int j = 0; j < 4; j++) {
            float dv = 2.f * acc[r][j] - sqn[r] - sqj[j];
            unsigned bits = __float_as_uint(dv);
            unsigned key = (bits & 0x80000000u) ? ~bits : (bits | 0x80000000u);
            int m = 4 * t + j;
            cand[r][j] = ((ull)key << 10) | (unsigned)(1023 - m);
        }
        ull c0 = cand[r][0], c1 = cand[r][1], c2 = cand[r][2], c3 = cand[r][3], tmp;
        if (c1 > c0) { tmp = c0; c0 = c1; c1 = tmp; }
        if (c3 > c2) { tmp = c2; c2 = c3; c3 = tmp; }
        if (c2 > c0) { tmp = c0; c0 = c2; c2 = tmp; }
        if (c3 > c1) { tmp = c1; c1 = c3; c3 = tmp; }
        if (c2 > c1) { tmp = c1; c1 = c2; c2 = tmp; }
        cand[r][0] = c0; cand[r][1] = c1; cand[r][2] = c2; cand[r][3] = c3;
    }

    // phase 1: each warp emits ITS top-20 per row (warp-local, no block syncs)
    int ptr[NB] = {0, 0, 0, 0};
    for (int k = 0; k < KK; k++) {
#pragma unroll
        for (int r = 0; r < NB; r++) {
            int p = ptr[r];
            ull h = (p == 0) ? cand[r][0] : (p == 1) ? cand[r][1]
                  : (p == 2) ? cand[r][2] : (p == 3) ? cand[r][3] : 0ULL;
            unsigned hk = (unsigned)(h >> 10);
            unsigned wm = __reduce_max_sync(0xffffffffu, hk);
            unsigned bal = __ballot_sync(0xffffffffu, hk == wm);
            if (lane == __ffs(bal) - 1) {    // lowest lane = smallest m among ties
                lists[r][wid * KK + k] = h;
                ptr[r] = p + 1;
            }
        }
    }
    __syncthreads();

    // phase 2: warp r (<4) merges row r's 160 candidates (warp-local)
    if (wid < NB) {
        int r = wid;
        ull c5[5];
#pragma unroll
        for (int j = 0; j < 5; j++) c5[j] = lists[r][j * 32 + lane];
        // sort 5 desc (optimal 9-comparator network)
        ull tmp;
#define CASD(a, bq) { if (c5[bq] > c5[a]) { tmp = c5[a]; c5[a] = c5[bq]; c5[bq] = tmp; } }
        CASD(0, 1) CASD(3, 4) CASD(2, 4) CASD(2, 3) CASD(1, 4)
        CASD(0, 3) CASD(0, 2) CASD(1, 3) CASD(1, 2)
#undef CASD
        int p = 0;
        size_t ob = ((size_t)b * NN + nb0 + r) * KK;
        for (int k = 0; k < KK; k++) {
            ull h = (p == 0) ? c5[0] : (p == 1) ? c5[1] : (p == 2) ? c5[2]
                  : (p == 3) ? c5[3] : (p == 4) ? c5[4] : 0ULL;
            unsigned hk = (unsigned)(h >> 10);
            unsigned gm = __reduce_max_sync(0xffffffffu, hk);
            unsigned tv = (hk == gm) ? (unsigned)(h & 1023ULL) : 0u;  // larger = smaller m
            unsigned gt = __reduce_max_sync(0xffffffffu, tv);
            unsigned bal = __ballot_sync(0xffffffffu, (hk == gm) && (tv == gt));
            if (lane == __ffs(bal) - 1) {
                d_knnIdx[ob + k] = 1023 - (int)(h & 1023ULL);
                p++;
            }
        }
    }
}

// ---------------- per-point GEMM v2: no smem, uniform LDG.128 weights, o-split ----------------
template <int C, int O, int OG, int WOFF>
__global__ void __launch_bounds__(96) gemm2(const float* __restrict__ x,
                                            float* __restrict__ pad,
                                            float* __restrict__ ctrb) {
    constexpr int Cp = (C + 1) & ~1;
    constexpr int OC = (O + OG - 1) / OG;
    int b = blockIdx.x / (NN / 32);
    int tile = blockIdx.x % (NN / 32);
    int og = blockIdx.y;
    int t = threadIdx.x;
    int n = tile * 32 + (t & 31);
    int ax = t >> 5;

    float xr[Cp];
#pragma unroll
    for (int c = 0; c < C; c++)
        xr[c] = x[(((size_t)b * C + c) * 3 + ax) * NN + n];
    if (Cp > C) xr[Cp - 1] = 0.f;

    int o0 = og * OC;
    int o1 = (o0 + OC < O) ? o0 + OC : O;
    const float4* W4 = d_w4 + WOFF;
    size_t obase = (size_t)(b * NN + n) * (O * 8) + ax * 2;

    for (int o = o0; o < o1; o++) {
        float pa = 0.f, pb = 0.f, da = 0.f, db = 0.f;
#pragma unroll
        for (int cc = 0; cc < Cp; cc += 2) {
            float4 w0 = W4[o * Cp + cc];
            float4 w1 = W4[o * Cp + cc + 1];
            float x0 = xr[cc], x1v = xr[cc + 1];
            pa += w0.x * x0 + w1.x * x1v;
            pb += w0.y * x0 + w1.y * x1v;
            da += w0.z * x0 + w1.z * x1v;
            db += w0.w * x0 + w1.w * x1v;
        }
        *(float2*)&pad[obase + o * 8]  = make_float2(pa, da);
        *(float2*)&ctrb[obase + o * 8] = make_float2(pb, db);
    }
}

// ---------------- edge combine + leaky + learned max-pool (dynamic smem, KC=4) ----------------
template <int O, int OPT, int NP>
__global__ void __launch_bounds__(32 * NP) edge_combine(const float* __restrict__ pad,
                                                        const float* __restrict__ ctrb,
                                                        const float* __restrict__ Wm,
                                                        float* __restrict__ out) {
    constexpr int AT = (O + OPT - 1) / OPT;   // active lanes
    constexpr int Opad = AT * OPT;
    constexpr int KC = 4;
    constexpr int T = 32 * NP;

    extern __shared__ float4 sm4[];
    float4* h4s = sm4;                              // NP*KC*Opad float4
    float*  WmT = (float*)(sm4 + NP * KC * Opad);   // O*Opad floats
    int*    kk  = (int*)(WmT + O * Opad);           // NP*KK ints

    int b = blockIdx.x / (NN / NP);
    int ptile = blockIdx.x % (NN / NP);
    int t = threadIdx.x;
    int w = t >> 5, lane = t & 31;

    for (int i = t; i < O * O; i += T) {
        int o = i / O, c = i - o * O;
        WmT[c * Opad + o] = Wm[i];
    }
    if constexpr (Opad > O) {
        for (int i = t; i < O * (Opad - O); i += T) {
            int c = i / (Opad - O), j = i - c * (Opad - O);
            WmT[c * Opad + O + j] = 0.f;
        }
    }
    int n = ptile * NP + w;
    if (lane < KK) kk[w * KK + lane] = d_knnIdx[((size_t)b * NN + n) * KK + lane];
    __syncthreads();

    bool act = lane < AT;
    float pb[OPT][3], db[OPT][3];
    size_t cbase = (size_t)(b * NN + n) * (O * 8);
    if (act) {
#pragma unroll
        for (int j = 0; j < OPT; j++) {
            int o = lane * OPT + j;
            float4 u  = *(const float4*)&ctrb[cbase + o * 8];
            float2 u2 = *(const float2*)&ctrb[cbase + o * 8 + 4];
            pb[j][0] = u.x;  db[j][0] = u.y;
            pb[j][1] = u.z;  db[j][1] = u.w;
            pb[j][2] = u2.x; db[j][2] = u2.y;
        }
    }

    float best[OPT];
    float bh[OPT][3];
#pragma unroll
    for (int j = 0; j < OPT; j++) { best[j] = -CUDART_INF_F; bh[j][0] = bh[j][1] = bh[j][2] = 0.f; }

    for (int chunk = 0; chunk < KK / KC; chunk++) {
#pragma unroll
        for (int kc = 0; kc < KC; kc++) {
            int m = kk[w * KK + chunk * KC + kc];
            if (act) {
                size_t gbase = (size_t)(b * NN + m) * (O * 8);
#pragma unroll
                for (int j = 0; j < OPT; j++) {
                    int o = lane * OPT + j;
                    float4 u  = *(const float4*)&pad[gbase + o * 8];
                    float2 u2 = *(const float2*)&pad[gbase + o * 8 + 4];
                    float p0 = u.x  + pb[j][0], q0 = u.y  + db[j][0];
                    float p1 = u.z  + pb[j][1], q1 = u.w  + db[j][1];
                    float p2 = u2.x + pb[j][2], q2 = u2.y + db[j][2];
                    float dot = p0 * q0 + p1 * q1 + p2 * q2;
                    float h0, h1, h2;
                    if (dot >= 0.f) {
                        h0 = p0; h1 = p1; h2 = p2;
                    } else {
                        float dsq = q0 * q0 + q1 * q1 + q2 * q2;
                        float cth = 0.8f * dot / (dsq + 1e-6f);
                        h0 = p0 - cth * q0; h1 = p1 - cth * q1; h2 = p2 - cth * q2;
                    }
                    h4s[(w * KC + kc) * Opad + lane * OPT + j] = make_float4(h0, h1, h2, 0.f);
                }
            }
        }
        __syncwarp();
        if (act) {
            float mv[OPT][KC][3];
#pragma unroll
            for (int j = 0; j < OPT; j++)
#pragma unroll
                for (int kc = 0; kc < KC; kc++) mv[j][kc][0] = mv[j][kc][1] = mv[j][kc][2] = 0.f;
#pragma unroll 2
            for (int c = 0; c < O; c++) {
                float wv[OPT];
#pragma unroll
                for (int j = 0; j < OPT; j++) wv[j] = WmT[c * Opad + lane * OPT + j];
#pragma unroll
                for (int kc = 0; kc < KC; kc++) {
                    float4 hc = h4s[(w * KC + kc) * Opad + c];
#pragma unroll
                    for (int j = 0; j < OPT; j++) {
                        mv[j][kc][0] += wv[j] * hc.x;
                        mv[j][kc][1] += wv[j] * hc.y;
                        mv[j][kc][2] += wv[j] * hc.z;
                    }
                }
            }
#pragma unroll
            for (int kc = 0; kc < KC; kc++) {
#pragma unroll
                for (int j = 0; j < OPT; j++) {
                    float4 hj = h4s[(w * KC + kc) * Opad + lane * OPT + j];
                    float pd = hj.x * mv[j][kc][0] + hj.y * mv[j][kc][1] + hj.z * mv[j][kc][2];
                    if (pd > best[j]) {   // first max wins (k ascending)
                        best[j] = pd;
                        bh[j][0] = hj.x; bh[j][1] = hj.y; bh[j][2] = hj.z;
                    }
                }
            }
        }
        __syncwarp();
    }

    if (act) {
#pragma unroll
        for (int j = 0; j < OPT; j++) {
            int o = lane * OPT + j;
            if (o < O) {
                float* op = out + (((size_t)b * O + o) * 3) * NN + n;
                op[0]      = bh[j][0];
                op[NN]     = bh[j][1];
                op[2 * NN] = bh[j][2];
            }
        }
    }
}

// ---------------- layer 5: vn_leaky on concat(x1..x4) -> (B,1023,N) ----------------
__global__ void __launch_bounds__(352) layer5_kernel(const float* __restrict__ Wd5) {
    constexpr int NP = 4;
    __shared__ float4 es[NP][169];
    __shared__ float dvs[NP][4];

    int b = blockIdx.x / (NN / NP);
    int tile = blockIdx.x % (NN / NP);
    int t = threadIdx.x;

    for (int idx = t; idx < NP * 169; idx += 352) {
        int p = idx / 169, c = idx - p * 169;
        int n = tile * NP + p;
        const float* src; int cc, CL;
        if (c < 21)      { src = d_x1; cc = c;      CL = 21; }
        else if (c < 42) { src = d_x2; cc = c - 21; CL = 21; }
        else if (c < 84) { src = d_x3; cc = c - 42; CL = 42; }
        else             { src = d_x4; cc = c - 84; CL = 85; }
        size_t base = (((size_t)b * CL + cc) * 3) * NN + n;
        es[p][c] = make_float4(src[base], src[base + NN], src[base + 2 * NN], 0.f);
    }
    __syncthreads();

    if (t < NP) {
        int p = t;
        float s0 = 0.f, s1 = 0.f, s2 = 0.f;
        for (int c = 0; c < 169; c++) {
            float wv = Wd5[c];
            float4 e = es[p][c];
            s0 += wv * e.x; s1 += wv * e.y; s2 += wv * e.z;
        }
        dvs[p][0] = s0; dvs[p][1] = s1; dvs[p][2] = s2;
        dvs[p][3] = 0.8f / (s0 * s0 + s1 * s1 + s2 * s2 + 1e-6f);
    }
    __syncthreads();

    int o = t;
    if (o < 341) {
        float a[NP][3];
#pragma unroll
        for (int p = 0; p < NP; p++) a[p][0] = a[p][1] = a[p][2] = 0.f;
        const float* wc = d_wp5t + o;
#pragma unroll 2
        for (int c = 0; c < 169; c++) {
            float wv = wc[(size_t)c * 341];
#pragma unroll
            for (int p = 0; p < NP; p++) {
                float4 e = es[p][c];
                a[p][0] += wv * e.x; a[p][1] += wv * e.y; a[p][2] += wv * e.z;
            }
        }
#pragma unroll
        for (int p = 0; p < NP; p++) {
            int n = tile * NP + p;
            float dot = a[p][0] * dvs[p][0] + a[p][1] * dvs[p][1] + a[p][2] * dvs[p][2];
            float h0, h1, h2;
            if (dot >= 0.f) { h0 = a[p][0]; h1 = a[p][1]; h2 = a[p][2]; }
            else {
                float cth = dot * dvs[p][3];
                h0 = a[p][0] - cth * dvs[p][0];
                h1 = a[p][1] - cth * dvs[p][1];
                h2 = a[p][2] - cth * dvs[p][2];
            }
            size_t base = ((size_t)b * 1023 + o * 3) * NN + n;
            d_h5[base]          = h0;
            d_h5[base + NN]     = h1;
            d_h5[base + 2 * NN] = h2;
        }
    }
}

// ---------------- global max + mean over N ----------------
__global__ void reduce_kernel() {
    int b = blockIdx.x / 1023;
    int ch = blockIdx.x - b * 1023;
    const float* row = d_h5 + (size_t)b * 1023 * NN + (size_t)ch * NN;
    int t = threadIdx.x;
    float mx = -CUDART_INF_F, sm = 0.f;
    for (int m = t; m < NN; m += 128) {
        float v = row[m];
        mx = fmaxf(mx, v);
        sm += v;
    }
    __shared__ float smx[128], ssm[128];
    smx[t] = mx; ssm[t] = sm;
    __syncthreads();
    for (int s = 64; s > 0; s >>= 1) {
        if (t < s) { smx[t] = fmaxf(smx[t], smx[t + s]); ssm[t] += ssm[t + s]; }
        __syncthreads();
    }
    if (t == 0) {
        d_g[b * 2046 + ch]        = smx[0];
        d_g[b * 2046 + 1023 + ch] = ssm[0] * (1.f / NN);
    }
}

// ---------------- FC: one warp per output element ----------------
__global__ void fc_kernel(const float* __restrict__ in, const float* __restrict__ W,
                          const float* __restrict__ bias, float* __restrict__ out,
                          int rows, int icols, int ocols, float slope) {
    int gw = (blockIdx.x * blockDim.x + threadIdx.x) >> 5;
    int lane = threadIdx.x & 31;
    if (gw >= rows * ocols) return;
    int r = gw / ocols;
    int o = gw - r * ocols;
    const float* ir = in + (size_t)r * icols;
    const float* wr = W + (size_t)o * icols;
    float s = 0.f;
    for (int c = lane; c < icols; c += 32) s += ir[c] * wr[c];
#pragma unroll
    for (int off = 16; off; off >>= 1) s += __shfl_down_sync(0xffffffffu, s, off);
    if (lane == 0) {
        s += bias[o];
        if (slope != 1.0f) s = (s >= 0.f) ? s : slope * s;
        out[(size_t)r * ocols + o] = s;
    }
}

// ---------------- launch ----------------
extern "C" void kernel_launch(void* const* d_in, const int* in_sizes, int n_in,
                              void* d_out, int out_size) {
    const float* x   = (const float*)d_in[0];
    const float* Wp1 = (const float*)d_in[1];
    const float* Wd1 = (const float*)d_in[2];
    const float* Wm1 = (const float*)d_in[3];
    const float* Wp2 = (const float*)d_in[4];
    const float* Wd2 = (const float*)d_in[5];
    const float* Wm2 = (const float*)d_in[6];
    const float* Wp3 = (const float*)d_in[7];
    const float* Wd3 = (const float*)d_in[8];
    const float* Wm3 = (const float*)d_in[9];
    const float* Wp4 = (const float*)d_in[10];
    const float* Wd4 = (const float*)d_in[11];
    const float* Wm4 = (const float*)d_in[12];
    const float* Wp5 = (const float*)d_in[13];
    const float* Wd5 = (const float*)d_in[14];
    const float* W1  = (const float*)d_in[15];
    const float* b1  = (const float*)d_in[16];
    const float* W2  = (const float*)d_in[17];
    const float* b2  = (const float*)d_in[18];
    const float* W3  = (const float*)d_in[19];
    const float* b3  = (const float*)d_in[20];

    float *f0, *x1, *x2, *x3, *x4, *pad, *ctrb, *g, *g1, *g2;
    cudaGetSymbolAddress((void**)&f0,   d_f0);
    cudaGetSymbolAddress((void**)&x1,   d_x1);
    cudaGetSymbolAddress((void**)&x2,   d_x2);
    cudaGetSymbolAddress((void**)&x3,   d_x3);
    cudaGetSymbolAddress((void**)&x4,   d_x4);
    cudaGetSymbolAddress((void**)&pad,  d_pad);
    cudaGetSymbolAddress((void**)&ctrb, d_ctr);
    cudaGetSymbolAddress((void**)&g,    d_g);
    cudaGetSymbolAddress((void**)&g1,   d_g1);
    cudaGetSymbolAddress((void**)&g2,   d_g2);

    // dynamic smem for edge_combine: h4s (NP*4*Opad float4) + WmT (O*Opad) + kk (NP*20 int)
    const int sz12 = 8 * 4 * 21 * 16 + 21 * 21 * 4 + 8 * KK * 4;   // 13156
    const int sz3  = 8 * 4 * 42 * 16 + 42 * 42 * 4 + 8 * KK * 4;   // 29200
    const int sz4  = 4 * 4 * 87 * 16 + 85 * 87 * 4 + 4 * KK * 4;   // 52172 (>48KB)
    cudaFuncSetAttribute(edge_combine<85, 3, 4>, cudaFuncAttributeMaxDynamicSharedMemorySize, sz4);

    transpose_kernel<<<(BB * NN * 3 + 255) / 256, 256>>>(x);
    transpose_w5<<<(341 * 169 + 255) / 256, 256>>>(Wp5);
    w4_prep<<<(4998 + 255) / 256, 256>>>(Wp1, Wd1, Wp2, Wd2, Wp3, Wd3, Wp4, Wd4);

    sq_kernel<3><<<BB * NN / 256, 256>>>(f0);
    knn_kernel<3><<<BB * NN / 4, 256>>>(f0);
    gemm2<1, 21, 2, 0><<<dim3(BB * (NN / 32), 2), 96>>>(f0, pad, ctrb);
    edge_combine<21, 1, 8><<<BB * NN / 8, 256, sz12>>>(pad, ctrb, Wm1, x1);

    sq_kernel<63><<<BB * NN / 256, 256>>>(x1);
    knn_kernel<63><<<BB * NN / 4, 256>>>(x1);
    gemm2<21, 21, 2, 42><<<dim3(BB * (NN / 32), 2), 96>>>(x1, pad, ctrb);
    edge_combine<21, 1, 8><<<BB * NN / 8, 256, sz12>>>(pad, ctrb, Wm2, x2);

    sq_kernel<63><<<BB * NN / 256, 256>>>(x2);
    knn_kernel<63><<<BB * NN / 4, 256>>>(x2);
    gemm2<21, 42, 2, 504><<<dim3(BB * (NN / 32), 2), 96>>>(x2, pad, ctrb);
    edge_combine<42, 2, 8><<<BB * NN / 8, 256, sz3>>>(pad, ctrb, Wm3, x3);

    sq_kernel<126><<<BB * NN / 256, 256>>>(x3);
    knn_kernel<126><<<BB * NN / 4, 256>>>(x3);
    gemm2<42, 85, 4, 1428><<<dim3(BB * (NN / 32), 4), 96>>>(x3, pad, ctrb);
    edge_combine<85, 3, 4><<<BB * NN / 4, 128, sz4>>>(pad, ctrb, Wm4, x4);

    layer5_kernel<<<BB * NN / 4, 352>>>(Wd5);
    reduce_kernel<<<BB * 1023, 128>>>();

    fc_kernel<<<(8 * 512 * 32 + 255) / 256, 256>>>(g,  W1, b1, g1, 8, 2046, 512, 0.01f);
    fc_kernel<<<(8 * 256 * 32 + 255) / 256, 256>>>(g1, W2, b2, g2, 8, 512,  256, 0.01f);
    fc_kernel<<<(8 * 128 * 32 + 255) / 256, 256>>>(g2, W3, b3, (float*)d_out, 8, 256, 128, 1.0f);
}